// round 11
// baseline (speedup 1.0000x reference)
#include <cuda_runtime.h>
#include <cuda_bf16.h>
#include <cstdint>

#define BATCH   8
#define SEQ     4096
#define D_HID   1024
#define N_HEADS 16
#define D_HEAD  64
#define M_TOT   (BATCH * SEQ)     // 32768
#define N_TOT   (3 * D_HID)       // 3072
#define K_TOT   (D_HID)           // 1024

// Scratch (allocation-free rule: __device__ globals)
__device__ __nv_bfloat16 g_qkvh[(size_t)M_TOT * N_TOT];   // qkv hi plane
__device__ __nv_bfloat16 g_qkvl[(size_t)M_TOT * N_TOT];   // qkv lo plane
__device__ float g_part[(size_t)8 * 128 * 4096];
__device__ __nv_bfloat16 g_ath[(size_t)128 * 4096];       // attn^T [bh][e][d] hi
__device__ __nv_bfloat16 g_atl[(size_t)128 * 4096];       // attn^T lo
__device__ __nv_bfloat16 g_xh[(size_t)M_TOT * K_TOT];
__device__ __nv_bfloat16 g_xl[(size_t)M_TOT * K_TOT];
__device__ __nv_bfloat16 g_wth[(size_t)N_TOT * K_TOT];
__device__ __nv_bfloat16 g_wtl[(size_t)N_TOT * K_TOT];

// ---------------------------------------------------------------------------
// helpers
// ---------------------------------------------------------------------------
__device__ __forceinline__ uint32_t smem_u32(const void* p) {
    uint32_t a;
    asm("{ .reg .u64 t; cvta.to.shared.u64 t, %1; cvt.u32.u64 %0, t; }" : "=r"(a) : "l"(p));
    return a;
}
__device__ __forceinline__ void cp16(uint32_t smem_dst, const void* gsrc) {
    asm volatile("cp.async.cg.shared.global [%0], [%1], 16;" :: "r"(smem_dst), "l"(gsrc));
}
__device__ __forceinline__ void cp_commit() {
    asm volatile("cp.async.commit_group;" ::: "memory");
}
__device__ __forceinline__ void ldsm4(uint32_t* r, uint32_t addr) {
    asm volatile("ldmatrix.sync.aligned.m8n8.x4.shared.b16 {%0,%1,%2,%3}, [%4];"
                 : "=r"(r[0]), "=r"(r[1]), "=r"(r[2]), "=r"(r[3]) : "r"(addr));
}
__device__ __forceinline__ void ldsm4t(uint32_t* r, uint32_t addr) {
    asm volatile("ldmatrix.sync.aligned.m8n8.x4.trans.shared.b16 {%0,%1,%2,%3}, [%4];"
                 : "=r"(r[0]), "=r"(r[1]), "=r"(r[2]), "=r"(r[3]) : "r"(addr));
}
__device__ __forceinline__ void mma16816(float* c, const uint32_t* a, const uint32_t* b) {
    asm volatile("mma.sync.aligned.m16n8k16.row.col.f32.bf16.bf16.f32 "
                 "{%0,%1,%2,%3}, {%4,%5,%6,%7}, {%8,%9}, {%0,%1,%2,%3};"
                 : "+f"(c[0]), "+f"(c[1]), "+f"(c[2]), "+f"(c[3])
                 : "r"(a[0]), "r"(a[1]), "r"(a[2]), "r"(a[3]), "r"(b[0]), "r"(b[1]));
}
__device__ __forceinline__ uint32_t pack_bf16(float x, float y) {
    __nv_bfloat162 t = __floats2bfloat162_rn(x, y);
    return *reinterpret_cast<uint32_t*>(&t);
}

// ---------------------------------------------------------------------------
// Conversion kernels (fp32 -> bf16 hi/lo split)
// ---------------------------------------------------------------------------
__global__ __launch_bounds__(256) void convert_x_kernel(const float* __restrict__ x)
{
    size_t i = ((size_t)blockIdx.x * 256 + threadIdx.x) * 8;
    float4 a = *(const float4*)(x + i);
    float4 b = *(const float4*)(x + i + 4);
    float v[8] = {a.x, a.y, a.z, a.w, b.x, b.y, b.z, b.w};
    __nv_bfloat16 hi[8], lo[8];
#pragma unroll
    for (int j = 0; j < 8; j++) {
        hi[j] = __float2bfloat16(v[j]);
        lo[j] = __float2bfloat16(v[j] - __bfloat162float(hi[j]));
    }
    *(uint4*)(g_xh + i) = *(uint4*)hi;
    *(uint4*)(g_xl + i) = *(uint4*)lo;
}

__global__ __launch_bounds__(256) void convert_w_kernel(const float* __restrict__ W)
{
    __shared__ float t[32][33];
    int x0 = blockIdx.x * 32;
    int y0 = blockIdx.y * 32;
    int tx = threadIdx.x, ty = threadIdx.y;
#pragma unroll
    for (int j = 0; j < 4; j++)
        t[ty + j * 8][tx] = W[(size_t)(y0 + ty + j * 8) * N_TOT + x0 + tx];
    __syncthreads();
#pragma unroll
    for (int j = 0; j < 4; j++) {
        int n = x0 + ty + j * 8;
        int k = y0 + tx;
        float v = t[tx][ty + j * 8];
        __nv_bfloat16 hi = __float2bfloat16(v);
        __nv_bfloat16 lo = __float2bfloat16(v - __bfloat162float(hi));
        g_wth[(size_t)n * K_TOT + k] = hi;
        g_wtl[(size_t)n * K_TOT + k] = lo;
    }
}

// ---------------------------------------------------------------------------
// K1: qkv = x @ W + b, mma.sync bf16 3-term split, single K pass.
// Block 256x128, BK=32, 32 k-chunks, 4 stages x 48KB, ONE sync per chunk,
// prefetch distance 3. 512 threads, 16 warps, warp tile 32x64.
// 64B rows, swizzle off = r*64 + ((c ^ ((r>>1)&3))<<4).
// ---------------------------------------------------------------------------
#define BM 256
#define BN 128
#define BK 32
#define NCHUNK 32
#define STAGE_BYTES 49152            // xh 16K | xl 16K | wh 8K | wl 8K
#define XH_OFF(s) ((s) * STAGE_BYTES)
#define XL_OFF(s) ((s) * STAGE_BYTES + 16384)
#define WH_OFF(s) ((s) * STAGE_BYTES + 32768)
#define WL_OFF(s) ((s) * STAGE_BYTES + 40960)
#define GEMM_SMEM (4 * STAGE_BYTES)  // 192 KB

#define SWZ64(r, c) ((uint32_t)((r) * 64 + ((((c) ^ (((r) >> 1) & 3))) << 4)))

__device__ __forceinline__ void load_chunk(uint32_t sb, int tid, int by, int bx, int c, int s)
{
    int koff = c * BK;
    const __nv_bfloat16* Ah = g_xh  + (size_t)(by * BM) * K_TOT + koff;
    const __nv_bfloat16* Al = g_xl  + (size_t)(by * BM) * K_TOT + koff;
    const __nv_bfloat16* Bh = g_wth + (size_t)(bx * BN) * K_TOT + koff;
    const __nv_bfloat16* Bl = g_wtl + (size_t)(bx * BN) * K_TOT + koff;
#pragma unroll
    for (int i = 0; i < 2; i++) {            // A planes: 1024 slots each
        int slot = i * 512 + tid;
        int r  = slot >> 2;
        int c4 = slot & 3;
        uint32_t off = SWZ64(r, c4);
        cp16(sb + XH_OFF(s) + off, Ah + (size_t)r * K_TOT + c4 * 8);
        cp16(sb + XL_OFF(s) + off, Al + (size_t)r * K_TOT + c4 * 8);
    }
    {                                        // B planes: 512 slots each
        int r  = tid >> 2;
        int c4 = tid & 3;
        uint32_t off = SWZ64(r, c4);
        cp16(sb + WH_OFF(s) + off, Bh + (size_t)r * K_TOT + c4 * 8);
        cp16(sb + WL_OFF(s) + off, Bl + (size_t)r * K_TOT + c4 * 8);
    }
}

__global__ __launch_bounds__(512, 1) void qkv_mma_kernel(const float* __restrict__ bias)
{
    extern __shared__ __align__(128) uint8_t smem[];
    uint32_t sb = smem_u32(smem);
    const int tid  = threadIdx.x;
    const int wid  = tid >> 5;
    const int lane = tid & 31;
    const int bx = blockIdx.x;    // N tile 0..23
    const int by = blockIdx.y;    // M tile 0..127
    const int wm = wid >> 1;      // 0..7  (32 M each)
    const int wn = wid & 1;       // 0..1  (64 N each)

    float acc[2][8][4];
#pragma unroll
    for (int mt = 0; mt < 2; mt++)
#pragma unroll
        for (int nt = 0; nt < 8; nt++)
#pragma unroll
            for (int j = 0; j < 4; j++) acc[mt][nt][j] = 0.f;

    load_chunk(sb, tid, by, bx, 0, 0); cp_commit();
    load_chunk(sb, tid, by, bx, 1, 1); cp_commit();
    load_chunk(sb, tid, by, bx, 2, 2); cp_commit();

    const int a_r = wm * 32 + (lane & 15);
    const int a_h = lane >> 4;
    const int b_r = wn * 64 + ((lane >> 4) << 3) + (lane & 7);
    const int b_h = (lane >> 3) & 1;

    for (int ch = 0; ch < NCHUNK; ch++) {
        asm volatile("cp.async.wait_group 2;" ::: "memory");   // chunk ch resident
        __syncthreads();   // data visible + compute(ch-1) done (its stage gets ch+3)
        if (ch + 3 < NCHUNK) load_chunk(sb, tid, by, bx, ch + 3, (ch + 3) & 3);
        cp_commit();

        const int s = ch & 3;
        const uint32_t xh_b = sb + XH_OFF(s);
        const uint32_t xl_b = sb + XL_OFF(s);
        const uint32_t wh_b = sb + WH_OFF(s);
        const uint32_t wl_b = sb + WL_OFF(s);
#pragma unroll
        for (int ks = 0; ks < 2; ks++) {
            uint32_t ah[2][4], al[2][4];
#pragma unroll
            for (int mt = 0; mt < 2; mt++) {
                int r = a_r + mt * 16;
                int c = ks * 2 + a_h;
                uint32_t off = SWZ64(r, c);
                ldsm4(ah[mt], xh_b + off);
                ldsm4(al[mt], xl_b + off);
            }
#pragma unroll
            for (int np = 0; np < 4; np++) {
                int r = b_r + np * 16;
                int c = ks * 2 + b_h;
                uint32_t off = SWZ64(r, c);
                uint32_t qh[4], ql[4];
                ldsm4(qh, wh_b + off);
                ldsm4(ql, wl_b + off);
#pragma unroll
                for (int mt = 0; mt < 2; mt++) {
                    mma16816(acc[mt][np * 2 + 0], ah[mt], qh + 0);
                    mma16816(acc[mt][np * 2 + 1], ah[mt], qh + 2);
                    mma16816(acc[mt][np * 2 + 0], al[mt], qh + 0);
                    mma16816(acc[mt][np * 2 + 1], al[mt], qh + 2);
                    mma16816(acc[mt][np * 2 + 0], ah[mt], ql + 0);
                    mma16816(acc[mt][np * 2 + 1], ah[mt], ql + 2);
                }
            }
        }
    }
    asm volatile("cp.async.wait_group 0;" ::: "memory");
    __syncthreads();

    // ---- Epilogue via smem staging (coalesced 16B stores) ----
    const int ncol0 = bx * BN + wn * 64 + (lane & 3) * 2;
    float b0[8], b1[8];
#pragma unroll
    for (int nt = 0; nt < 8; nt++) {
        b0[nt] = __ldg(bias + ncol0 + nt * 8);
        b1[nt] = __ldg(bias + ncol0 + nt * 8 + 1);
    }
#pragma unroll
    for (int mt = 0; mt < 2; mt++)
#pragma unroll
        for (int half = 0; half < 2; half++) {
            int m = wm * 32 + mt * 16 + (lane >> 2) + half * 8;   // 0..255 (local)
#pragma unroll
            for (int nt = 0; nt < 8; nt++) {
                float vx = acc[mt][nt][half * 2 + 0] + b0[nt];
                float vy = acc[mt][nt][half * 2 + 1] + b1[nt];
                __nv_bfloat16 hx = __float2bfloat16(vx);
                __nv_bfloat16 hy = __float2bfloat16(vy);
                int chunk = wn * 8 + nt;                          // 0..15
                uint32_t off = (uint32_t)(m * 256 + (((chunk ^ (m & 7)) << 4))
                                          + (lane & 3) * 4);
                *(uint32_t*)(smem + off) = pack_bf16(vx, vy);
                *(uint32_t*)(smem + 65536 + off) =
                    pack_bf16(vx - __bfloat162float(hx), vy - __bfloat162float(hy));
            }
        }
    __syncthreads();

#pragma unroll
    for (int i = 0; i < 8; i++) {
        int slot = i * 512 + tid;           // 0..4095
        int r = slot >> 4;                  // 0..255
        int c = slot & 15;                  // 16B chunk
        uint32_t soff = (uint32_t)(r * 256 + ((c ^ (r & 7)) << 4));
        uint4 hv = *(uint4*)(smem + soff);
        uint4 lv = *(uint4*)(smem + 65536 + soff);
        size_t gbase = (size_t)(by * BM + r) * N_TOT + bx * BN + c * 8;
        *(uint4*)(g_qkvh + gbase) = hv;
        *(uint4*)(g_qkvl + gbase) = lv;
    }
}

// ---------------------------------------------------------------------------
// K2a: partial S over a 512-n chunk, tensor cores, bf16 planes via ldmatrix.trans.
// grid (8, 128). 256 threads. Subtile 64n, 2-stage cp.async (64KB smem).
// ---------------------------------------------------------------------------
#define K2_SMEM 65536

__device__ __forceinline__ void k2_load_sub(uint32_t sb, int tid,
                                            const __nv_bfloat16* qh, const __nv_bfloat16* ql,
                                            const __nv_bfloat16* kh, const __nv_bfloat16* kl,
                                            int n0, int stg)
{
    const __nv_bfloat16* src[4] = {qh, ql, kh, kl};
    uint32_t base = sb + stg * 32768;
#pragma unroll
    for (int p = 0; p < 4; p++) {
#pragma unroll
        for (int i = 0; i < 2; i++) {
            int slot = i * 256 + tid;
            int r   = slot >> 3;
            int c16 = slot & 7;
            uint32_t off = (uint32_t)(r * 128 + ((c16 ^ (r & 7)) << 4));
            cp16(base + p * 8192 + off, src[p] + (size_t)(n0 + r) * N_TOT + c16 * 8);
        }
    }
}

__global__ __launch_bounds__(256) void attn_part_kernel()
{
    extern __shared__ __align__(128) uint8_t smem[];
    uint32_t sb = smem_u32(smem);
    const int tid   = threadIdx.x;
    const int wid   = tid >> 5;
    const int lane  = tid & 31;
    const int chunk = blockIdx.x;
    const int bh    = blockIdx.y;
    const int b     = bh >> 4, h = bh & 15;

    const __nv_bfloat16* qh = g_qkvh + (size_t)b * SEQ * N_TOT + h * 64;
    const __nv_bfloat16* ql = g_qkvl + (size_t)b * SEQ * N_TOT + h * 64;
    const __nv_bfloat16* kh = qh + D_HID;
    const __nv_bfloat16* kl = ql + D_HID;

    const int wm = wid >> 2;
    const int wn = wid & 3;

    const int an = ((lane >> 4) & 1) * 8 + (lane & 7);
    const int ac = ((lane >> 3) & 1);
    const int bn = ((lane >> 3) & 1) * 8 + (lane & 7);
    const int bc = wn * 2 + (lane >> 4);

    float acc[2][2][4];
#pragma unroll
    for (int mt = 0; mt < 2; mt++)
#pragma unroll
        for (int nt = 0; nt < 2; nt++)
#pragma unroll
            for (int j = 0; j < 4; j++) acc[mt][nt][j] = 0.f;

    const int nbase = chunk * 512;
    k2_load_sub(sb, tid, qh, ql, kh, kl, nbase, 0);
    cp_commit();

    for (int t = 0; t < 8; t++) {
        __syncthreads();
        if (t + 1 < 8) k2_load_sub(sb, tid, qh, ql, kh, kl, nbase + (t + 1) * 64, (t + 1) & 1);
        cp_commit();
        asm volatile("cp.async.wait_group 1;" ::: "memory");
        __syncthreads();

        uint32_t stg = sb + (t & 1) * 32768;
#pragma unroll
        for (int ks = 0; ks < 4; ks++) {
            uint32_t aqh[2][4], aql[2][4];
#pragma unroll
            for (int mt = 0; mt < 2; mt++) {
                int n   = ks * 16 + an;
                int c16 = wm * 4 + mt * 2 + ac;
                uint32_t off = (uint32_t)(n * 128 + ((c16 ^ (n & 7)) << 4));
                ldsm4t(aqh[mt], stg + off);
                ldsm4t(aql[mt], stg + 8192 + off);
            }
            uint32_t bkh[2][2], bkl[2][2];
            {
                int n   = ks * 16 + bn;
                uint32_t off = (uint32_t)(n * 128 + ((bc ^ (n & 7)) << 4));
                uint32_t q[4];
                ldsm4t(q, stg + 16384 + off);
                bkh[0][0] = q[0]; bkh[0][1] = q[1]; bkh[1][0] = q[2]; bkh[1][1] = q[3];
                ldsm4t(q, stg + 24576 + off);
                bkl[0][0] = q[0]; bkl[0][1] = q[1]; bkl[1][0] = q[2]; bkl[1][1] = q[3];
            }
#pragma unroll
            for (int mt = 0; mt < 2; mt++)
#pragma unroll
                for (int nt = 0; nt < 2; nt++) {
                    mma16816(acc[mt][nt], aqh[mt], bkh[nt]);
                    mma16816(acc[mt][nt], aqh[mt], bkl[nt]);
                    mma16816(acc[mt][nt], aql[mt], bkh[nt]);
                }
        }
    }

    float* pg = g_part + ((size_t)chunk * 128 + bh) * 4096;
#pragma unroll
    for (int mt = 0; mt < 2; mt++)
#pragma unroll
        for (int nt = 0; nt < 2; nt++)
#pragma unroll
            for (int half = 0; half < 2; half++) {
                int d = wm * 32 + mt * 16 + (lane >> 2) + half * 8;
                int e = wn * 16 + nt * 8 + (lane & 3) * 2;
                float2 v;
                v.x = acc[mt][nt][half * 2 + 0];
                v.y = acc[mt][nt][half * 2 + 1];
                *(float2*)(pg + d * 64 + e) = v;
            }
}

// ---------------------------------------------------------------------------
// K2b: reduce 8 partials, scale, softmax over e; emit attn^T bf16 hi/lo.
// ---------------------------------------------------------------------------
__global__ __launch_bounds__(256) void attn_softmax_kernel()
{
    __shared__ float S[64 * 68 + 128];
    float* mrow = S + 64 * 68;
    float* irow = mrow + 64;

    const int tid = threadIdx.x;
    const int bh  = blockIdx.x;

#pragma unroll
    for (int i = 0; i < 16; i++) {
        int flat = i * 256 + tid;
        float v = 0.f;
#pragma unroll
        for (int c = 0; c < 8; c++)
            v += g_part[((size_t)c * 128 + bh) * 4096 + flat];
        int d = flat >> 6, e = flat & 63;
        S[d * 68 + e] = v * 0.125f;
    }
    __syncthreads();

    if (tid < 64) {
        float m = -3.4e38f;
#pragma unroll
        for (int e = 0; e < 64; e++) m = fmaxf(m, S[tid * 68 + e]);
        float sum = 0.f;
#pragma unroll
        for (int e = 0; e < 64; e++) sum += __expf(S[tid * 68 + e] - m);
        mrow[tid] = m;
        irow[tid] = 1.f / sum;
    }
    __syncthreads();

    __nv_bfloat16* ah = g_ath + (size_t)bh * 4096;
    __nv_bfloat16* al = g_atl + (size_t)bh * 4096;
#pragma unroll
    for (int i = 0; i < 16; i++) {
        int flat = i * 256 + tid;
        int e = flat >> 6, d = flat & 63;
        float a = __expf(S[d * 68 + e] - mrow[d]) * irow[d];
        __nv_bfloat16 hi = __float2bfloat16(a);
        ah[flat] = hi;
        al[flat] = __float2bfloat16(a - __bfloat162float(hi));
    }
}

// ---------------------------------------------------------------------------
// K3: out[n,e] = sum_d v[n,d] * attn[d,e] via tensor cores.
// ---------------------------------------------------------------------------
__global__ __launch_bounds__(256) void out_mma_kernel(float* __restrict__ out)
{
    __shared__ __align__(128) uint8_t smem[49152];
    uint32_t sb = smem_u32(smem);
    const int tid  = threadIdx.x;
    const int wid  = tid >> 5;
    const int lane = tid & 31;
    const int bh   = blockIdx.y;
    const int b    = bh >> 4, h = bh & 15;
    const int nt0  = blockIdx.x * 128;

    const __nv_bfloat16* agh = g_ath + (size_t)bh * 4096;
    const __nv_bfloat16* agl = g_atl + (size_t)bh * 4096;
#pragma unroll
    for (int i = 0; i < 2; i++) {
        int slot = i * 256 + tid;
        int r = slot >> 3, c = slot & 7;
        uint32_t dst = (uint32_t)(r * 128 + ((c ^ (r & 7)) << 4));
        cp16(sb + 32768 + dst, agh + r * 64 + c * 8);
        cp16(sb + 40960 + dst, agl + r * 64 + c * 8);
    }
    const __nv_bfloat16* vgh = g_qkvh + ((size_t)b * SEQ + nt0) * N_TOT + 2 * D_HID + h * 64;
    const __nv_bfloat16* vgl = g_qkvl + ((size_t)b * SEQ + nt0) * N_TOT + 2 * D_HID + h * 64;
#pragma unroll
    for (int i = 0; i < 4; i++) {
        int slot = i * 256 + tid;
        int r = slot >> 3, c = slot & 7;
        uint32_t off = (uint32_t)(r * 128 + ((c ^ (r & 7)) << 4));
        cp16(sb + off,         vgh + (size_t)r * N_TOT + c * 8);
        cp16(sb + 16384 + off, vgl + (size_t)r * N_TOT + c * 8);
    }
    cp_commit();
    asm volatile("cp.async.wait_group 0;" ::: "memory");
    __syncthreads();

    const int wm = wid >> 1;
    const int wn = wid & 1;
    const int a_r0 = wm * 32 + (lane & 15);
    const int a_h  = lane >> 4;
    const int b_r0 = wn * 32 + ((lane >> 4) << 3) + (lane & 7);
    const int b_h  = (lane >> 3) & 1;

    float acc[2][4][4];
#pragma unroll
    for (int mt = 0; mt < 2; mt++)
#pragma unroll
        for (int nt = 0; nt < 4; nt++)
#pragma unroll
            for (int j = 0; j < 4; j++) acc[mt][nt][j] = 0.f;

#pragma unroll
    for (int ks = 0; ks < 4; ks++) {
        uint32_t avh[2][4], avl[2][4];
#pragma unroll
        for (int mt = 0; mt < 2; mt++) {
            int r   = a_r0 + mt * 16;
            int c16 = ks * 2 + a_h;
            uint32_t so = (uint32_t)(r * 128 + ((c16 ^ (r & 7)) << 4));
            ldsm4(avh[mt], sb + so);
            ldsm4(avl[mt], sb + 16384 + so);
        }
        uint32_t bah[4][2], bal[4][2];
#pragma unroll
        for (int np = 0; np < 2; np++) {
            int r   = b_r0 + np * 16;
            int c16 = ks * 2 + b_h;
            uint32_t so = (uint32_t)(r * 128 + ((c16 ^ (r & 7)) << 4));
            uint32_t q[4];
            ldsm4(q, sb + 32768 + so);
            bah[np * 2 + 0][0] = q[0]; bah[np * 2 + 0][1] = q[1];
            bah[np * 2 + 1][0] = q[2]; bah[np * 2 + 1][1] = q[3];
            ldsm4(q, sb + 40960 + so);
            bal[np * 2 + 0][0] = q[0]; bal[np * 2 + 0][1] = q[1];
            bal[np * 2 + 1][0] = q[2]; bal[np * 2 + 1][1] = q[3];
        }
#pragma unroll
        for (int mt = 0; mt < 2; mt++)
#pragma unroll
            for (int nt = 0; nt < 4; nt++) {
                mma16816(acc[mt][nt], avh[mt], bah[nt]);
                mma16816(acc[mt][nt], avh[mt], bal[nt]);
                mma16816(acc[mt][nt], avl[mt], bah[nt]);
            }
    }

#pragma unroll
    for (int mt = 0; mt < 2; mt++)
#pragma unroll
        for (int half = 0; half < 2; half++) {
            int n = nt0 + wm * 32 + mt * 16 + (lane >> 2) + half * 8;
            float* orow = out + ((size_t)b * SEQ + n) * D_HID + h * 64
                          + wn * 32 + (lane & 3) * 2;
#pragma unroll
            for (int nt = 0; nt < 4; nt++) {
                float2 v;
                v.x = acc[mt][nt][half * 2 + 0];
                v.y = acc[mt][nt][half * 2 + 1];
                *(float2*)(orow + nt * 8) = v;
            }
        }
}

// ---------------------------------------------------------------------------
extern "C" void kernel_launch(void* const* d_in, const int* in_sizes, int n_in,
                              void* d_out, int out_size)
{
    const float* x    = (const float*)d_in[0];
    const float* W    = (const float*)d_in[1];
    const float* bias = (const float*)d_in[2];
    float* out = (float*)d_out;

    convert_x_kernel<<<(M_TOT * K_TOT) / (256 * 8), 256>>>(x);
    convert_w_kernel<<<dim3(N_TOT / 32, K_TOT / 32), dim3(32, 8)>>>(W);

    cudaFuncSetAttribute(qkv_mma_kernel, cudaFuncAttributeMaxDynamicSharedMemorySize, GEMM_SMEM);
    qkv_mma_kernel<<<dim3(N_TOT / BN, M_TOT / BM), 512, GEMM_SMEM>>>(bias);

    cudaFuncSetAttribute(attn_part_kernel, cudaFuncAttributeMaxDynamicSharedMemorySize, K2_SMEM);
    attn_part_kernel<<<dim3(8, BATCH * N_HEADS), 256, K2_SMEM>>>();

    attn_softmax_kernel<<<BATCH * N_HEADS, 256>>>();

    out_mma_kernel<<<dim3(SEQ / 128, BATCH * N_HEADS), 256>>>(out);
}

// round 12
// speedup vs baseline: 1.0832x; 1.0832x over previous
#include <cuda_runtime.h>
#include <cuda_bf16.h>
#include <cstdint>

#define BATCH   8
#define SEQ     4096
#define D_HID   1024
#define N_HEADS 16
#define D_HEAD  64
#define M_TOT   (BATCH * SEQ)     // 32768
#define N_TOT   (3 * D_HID)       // 3072
#define K_TOT   (D_HID)           // 1024

// Scratch (allocation-free rule: __device__ globals)
__device__ __nv_bfloat16 g_qkvh[(size_t)M_TOT * N_TOT];   // qkv hi plane
__device__ __nv_bfloat16 g_qkvl[(size_t)M_TOT * N_TOT];   // qkv lo plane
__device__ float g_part[(size_t)16 * 128 * 4096];
__device__ __nv_bfloat16 g_ath[(size_t)128 * 4096];       // attn^T [bh][e][d] hi
__device__ __nv_bfloat16 g_atl[(size_t)128 * 4096];       // attn^T lo
__device__ __nv_bfloat16 g_xh[(size_t)M_TOT * K_TOT];
__device__ __nv_bfloat16 g_xl[(size_t)M_TOT * K_TOT];
__device__ __nv_bfloat16 g_wth[(size_t)N_TOT * K_TOT];
__device__ __nv_bfloat16 g_wtl[(size_t)N_TOT * K_TOT];

// ---------------------------------------------------------------------------
// helpers
// ---------------------------------------------------------------------------
__device__ __forceinline__ uint32_t smem_u32(const void* p) {
    uint32_t a;
    asm("{ .reg .u64 t; cvta.to.shared.u64 t, %1; cvt.u32.u64 %0, t; }" : "=r"(a) : "l"(p));
    return a;
}
__device__ __forceinline__ void cp16(uint32_t smem_dst, const void* gsrc) {
    asm volatile("cp.async.cg.shared.global [%0], [%1], 16;" :: "r"(smem_dst), "l"(gsrc));
}
__device__ __forceinline__ void cp_commit() {
    asm volatile("cp.async.commit_group;" ::: "memory");
}
__device__ __forceinline__ void ldsm4(uint32_t* r, uint32_t addr) {
    asm volatile("ldmatrix.sync.aligned.m8n8.x4.shared.b16 {%0,%1,%2,%3}, [%4];"
                 : "=r"(r[0]), "=r"(r[1]), "=r"(r[2]), "=r"(r[3]) : "r"(addr));
}
__device__ __forceinline__ void ldsm4t(uint32_t* r, uint32_t addr) {
    asm volatile("ldmatrix.sync.aligned.m8n8.x4.trans.shared.b16 {%0,%1,%2,%3}, [%4];"
                 : "=r"(r[0]), "=r"(r[1]), "=r"(r[2]), "=r"(r[3]) : "r"(addr));
}
__device__ __forceinline__ void mma16816(float* c, const uint32_t* a, const uint32_t* b) {
    asm volatile("mma.sync.aligned.m16n8k16.row.col.f32.bf16.bf16.f32 "
                 "{%0,%1,%2,%3}, {%4,%5,%6,%7}, {%8,%9}, {%0,%1,%2,%3};"
                 : "+f"(c[0]), "+f"(c[1]), "+f"(c[2]), "+f"(c[3])
                 : "r"(a[0]), "r"(a[1]), "r"(a[2]), "r"(a[3]), "r"(b[0]), "r"(b[1]));
}
__device__ __forceinline__ uint32_t pack_bf16(float x, float y) {
    __nv_bfloat162 t = __floats2bfloat162_rn(x, y);
    return *reinterpret_cast<uint32_t*>(&t);
}

// ---------------------------------------------------------------------------
// Conversion kernels (fp32 -> bf16 hi/lo split)
// ---------------------------------------------------------------------------
__global__ __launch_bounds__(256) void convert_x_kernel(const float* __restrict__ x)
{
    size_t i = ((size_t)blockIdx.x * 256 + threadIdx.x) * 8;
    float4 a = *(const float4*)(x + i);
    float4 b = *(const float4*)(x + i + 4);
    float v[8] = {a.x, a.y, a.z, a.w, b.x, b.y, b.z, b.w};
    __nv_bfloat16 hi[8], lo[8];
#pragma unroll
    for (int j = 0; j < 8; j++) {
        hi[j] = __float2bfloat16(v[j]);
        lo[j] = __float2bfloat16(v[j] - __bfloat162float(hi[j]));
    }
    *(uint4*)(g_xh + i) = *(uint4*)hi;
    *(uint4*)(g_xl + i) = *(uint4*)lo;
}

__global__ __launch_bounds__(256) void convert_w_kernel(const float* __restrict__ W)
{
    __shared__ float t[32][33];
    int x0 = blockIdx.x * 32;
    int y0 = blockIdx.y * 32;
    int tx = threadIdx.x, ty = threadIdx.y;
#pragma unroll
    for (int j = 0; j < 4; j++)
        t[ty + j * 8][tx] = W[(size_t)(y0 + ty + j * 8) * N_TOT + x0 + tx];
    __syncthreads();
#pragma unroll
    for (int j = 0; j < 4; j++) {
        int n = x0 + ty + j * 8;
        int k = y0 + tx;
        float v = t[tx][ty + j * 8];
        __nv_bfloat16 hi = __float2bfloat16(v);
        __nv_bfloat16 lo = __float2bfloat16(v - __bfloat162float(hi));
        g_wth[(size_t)n * K_TOT + k] = hi;
        g_wtl[(size_t)n * K_TOT + k] = lo;
    }
}

// ---------------------------------------------------------------------------
// K1: qkv = x @ W + b, mma.sync bf16 3-term split, SINGLE K pass.
// Block 256x128, BK=64, 16 k-chunks; per chunk load xh/xl/wh/wl planes and
// issue all 3 terms (hh, lh, hl) per fragment load. 512 threads, 16 warps,
// warp tile 32x64. 2 stages x 96KB. Epilogue staged via smem.
// (measured-best round-10 configuration, byte-identical)
// ---------------------------------------------------------------------------
#define BM 256
#define BN 128
#define BK 64
#define NCHUNK 16
#define STAGE_BYTES 98304            // xh 32K | xl 32K | wh 16K | wl 16K
#define XH_OFF(s) ((s) * STAGE_BYTES)
#define XL_OFF(s) ((s) * STAGE_BYTES + 32768)
#define WH_OFF(s) ((s) * STAGE_BYTES + 65536)
#define WL_OFF(s) ((s) * STAGE_BYTES + 81920)
#define GEMM_SMEM (2 * STAGE_BYTES)  // 192 KB

__device__ __forceinline__ void load_chunk(uint32_t sb, int tid, int by, int bx, int c, int s)
{
    int koff = c * BK;
    const __nv_bfloat16* Ah = g_xh  + (size_t)(by * BM) * K_TOT + koff;
    const __nv_bfloat16* Al = g_xl  + (size_t)(by * BM) * K_TOT + koff;
    const __nv_bfloat16* Bh = g_wth + (size_t)(bx * BN) * K_TOT + koff;
    const __nv_bfloat16* Bl = g_wtl + (size_t)(bx * BN) * K_TOT + koff;
#pragma unroll
    for (int i = 0; i < 4; i++) {            // A planes: 2048 slots each
        int slot = i * 512 + tid;
        int r   = slot >> 3;
        int c16 = slot & 7;
        uint32_t off = (uint32_t)(r * 128 + ((c16 ^ (r & 7)) * 16));
        cp16(sb + XH_OFF(s) + off, Ah + (size_t)r * K_TOT + c16 * 8);
        cp16(sb + XL_OFF(s) + off, Al + (size_t)r * K_TOT + c16 * 8);
    }
#pragma unroll
    for (int i = 0; i < 2; i++) {            // B planes: 1024 slots each
        int slot = i * 512 + tid;
        int r   = slot >> 3;
        int c16 = slot & 7;
        uint32_t off = (uint32_t)(r * 128 + ((c16 ^ (r & 7)) * 16));
        cp16(sb + WH_OFF(s) + off, Bh + (size_t)r * K_TOT + c16 * 8);
        cp16(sb + WL_OFF(s) + off, Bl + (size_t)r * K_TOT + c16 * 8);
    }
}

__global__ __launch_bounds__(512, 1) void qkv_mma_kernel(const float* __restrict__ bias)
{
    extern __shared__ __align__(128) uint8_t smem[];
    uint32_t sb = smem_u32(smem);
    const int tid  = threadIdx.x;
    const int wid  = tid >> 5;
    const int lane = tid & 31;
    const int bx = blockIdx.x;    // N tile 0..23
    const int by = blockIdx.y;    // M tile 0..127
    const int wm = wid >> 1;      // 0..7  (32 M each)
    const int wn = wid & 1;       // 0..1  (64 N each)

    float acc[2][8][4];
#pragma unroll
    for (int mt = 0; mt < 2; mt++)
#pragma unroll
        for (int nt = 0; nt < 8; nt++)
#pragma unroll
            for (int j = 0; j < 4; j++) acc[mt][nt][j] = 0.f;

    load_chunk(sb, tid, by, bx, 0, 0);
    cp_commit();

    const int a_r = wm * 32 + (lane & 15);
    const int a_h = lane >> 4;
    const int b_r = wn * 64 + ((lane >> 4) << 3) + (lane & 7);
    const int b_h = (lane >> 3) & 1;

    for (int ch = 0; ch < NCHUNK; ch++) {
        __syncthreads();   // everyone done reading the stage we're about to fill
        if (ch + 1 < NCHUNK) load_chunk(sb, tid, by, bx, ch + 1, (ch + 1) & 1);
        cp_commit();
        asm volatile("cp.async.wait_group 1;" ::: "memory");
        __syncthreads();

        const int s = ch & 1;
        const uint32_t xh_b = sb + XH_OFF(s);
        const uint32_t xl_b = sb + XL_OFF(s);
        const uint32_t wh_b = sb + WH_OFF(s);
        const uint32_t wl_b = sb + WL_OFF(s);
#pragma unroll
        for (int ks = 0; ks < 4; ks++) {
            uint32_t ah[2][4], al[2][4];
#pragma unroll
            for (int mt = 0; mt < 2; mt++) {
                int r   = a_r + mt * 16;
                int c16 = ks * 2 + a_h;
                uint32_t off = (uint32_t)(r * 128 + ((c16 ^ (r & 7)) * 16));
                ldsm4(ah[mt], xh_b + off);
                ldsm4(al[mt], xl_b + off);
            }
#pragma unroll
            for (int np = 0; np < 4; np++) {
                int r   = b_r + np * 16;
                int c16 = ks * 2 + b_h;
                uint32_t off = (uint32_t)(r * 128 + ((c16 ^ (r & 7)) * 16));
                uint32_t qh[4], ql[4];
                ldsm4(qh, wh_b + off);
                ldsm4(ql, wl_b + off);
#pragma unroll
                for (int mt = 0; mt < 2; mt++) {
                    mma16816(acc[mt][np * 2 + 0], ah[mt], qh + 0);
                    mma16816(acc[mt][np * 2 + 1], ah[mt], qh + 2);
                    mma16816(acc[mt][np * 2 + 0], al[mt], qh + 0);
                    mma16816(acc[mt][np * 2 + 1], al[mt], qh + 2);
                    mma16816(acc[mt][np * 2 + 0], ah[mt], ql + 0);
                    mma16816(acc[mt][np * 2 + 1], ah[mt], ql + 2);
                }
            }
        }
    }
    asm volatile("cp.async.wait_group 0;" ::: "memory");
    __syncthreads();

    // ---- Epilogue via smem staging (coalesced 16B stores) ----
    const int ncol0 = bx * BN + wn * 64 + (lane & 3) * 2;
    float b0[8], b1[8];
#pragma unroll
    for (int nt = 0; nt < 8; nt++) {
        b0[nt] = __ldg(bias + ncol0 + nt * 8);
        b1[nt] = __ldg(bias + ncol0 + nt * 8 + 1);
    }
#pragma unroll
    for (int mt = 0; mt < 2; mt++)
#pragma unroll
        for (int half = 0; half < 2; half++) {
            int m = wm * 32 + mt * 16 + (lane >> 2) + half * 8;   // 0..255 (local)
#pragma unroll
            for (int nt = 0; nt < 8; nt++) {
                float vx = acc[mt][nt][half * 2 + 0] + b0[nt];
                float vy = acc[mt][nt][half * 2 + 1] + b1[nt];
                __nv_bfloat16 hx = __float2bfloat16(vx);
                __nv_bfloat16 hy = __float2bfloat16(vy);
                int chunk = wn * 8 + nt;                          // 0..15
                uint32_t off = (uint32_t)(m * 256 + (((chunk ^ (m & 7)) << 4))
                                          + (lane & 3) * 4);
                *(uint32_t*)(smem + off) = pack_bf16(vx, vy);
                *(uint32_t*)(smem + 65536 + off) =
                    pack_bf16(vx - __bfloat162float(hx), vy - __bfloat162float(hy));
            }
        }
    __syncthreads();

#pragma unroll
    for (int i = 0; i < 8; i++) {
        int slot = i * 512 + tid;           // 0..4095
        int r = slot >> 4;                  // 0..255
        int c = slot & 15;                  // 16B chunk
        uint32_t soff = (uint32_t)(r * 256 + ((c ^ (r & 7)) << 4));
        uint4 hv = *(uint4*)(smem + soff);
        uint4 lv = *(uint4*)(smem + 65536 + soff);
        size_t gbase = (size_t)(by * BM + r) * N_TOT + bx * BN + c * 8;
        *(uint4*)(g_qkvh + gbase) = hv;
        *(uint4*)(g_qkvl + gbase) = lv;
    }
}

// ---------------------------------------------------------------------------
// K2a: partial S over a 256-n chunk, tensor cores, bf16 planes via ldmatrix.trans.
// grid (16, 128). 256 threads. Subtile 64n, 2-stage cp.async (64KB smem).
// ---------------------------------------------------------------------------
#define K2_SMEM 65536
#define K2_NCHUNK 16
#define K2_SUB 4                 // 256 n per chunk / 64 n per subtile

__device__ __forceinline__ void k2_load_sub(uint32_t sb, int tid,
                                            const __nv_bfloat16* qh, const __nv_bfloat16* ql,
                                            const __nv_bfloat16* kh, const __nv_bfloat16* kl,
                                            int n0, int stg)
{
    const __nv_bfloat16* src[4] = {qh, ql, kh, kl};
    uint32_t base = sb + stg * 32768;
#pragma unroll
    for (int p = 0; p < 4; p++) {
#pragma unroll
        for (int i = 0; i < 2; i++) {
            int slot = i * 256 + tid;
            int r   = slot >> 3;
            int c16 = slot & 7;
            uint32_t off = (uint32_t)(r * 128 + ((c16 ^ (r & 7)) << 4));
            cp16(base + p * 8192 + off, src[p] + (size_t)(n0 + r) * N_TOT + c16 * 8);
        }
    }
}

__global__ __launch_bounds__(256) void attn_part_kernel()
{
    extern __shared__ __align__(128) uint8_t smem[];
    uint32_t sb = smem_u32(smem);
    const int tid   = threadIdx.x;
    const int wid   = tid >> 5;
    const int lane  = tid & 31;
    const int chunk = blockIdx.x;        // 0..15
    const int bh    = blockIdx.y;        // 0..127
    const int b     = bh >> 4, h = bh & 15;

    const __nv_bfloat16* qh = g_qkvh + (size_t)b * SEQ * N_TOT + h * 64;
    const __nv_bfloat16* ql = g_qkvl + (size_t)b * SEQ * N_TOT + h * 64;
    const __nv_bfloat16* kh = qh + D_HID;
    const __nv_bfloat16* kl = ql + D_HID;

    const int wm = wid >> 2;
    const int wn = wid & 3;

    const int an = ((lane >> 4) & 1) * 8 + (lane & 7);
    const int ac = ((lane >> 3) & 1);
    const int bn = ((lane >> 3) & 1) * 8 + (lane & 7);
    const int bc = wn * 2 + (lane >> 4);

    float acc[2][2][4];
#pragma unroll
    for (int mt = 0; mt < 2; mt++)
#pragma unroll
        for (int nt = 0; nt < 2; nt++)
#pragma unroll
            for (int j = 0; j < 4; j++) acc[mt][nt][j] = 0.f;

    const int nbase = chunk * 256;
    k2_load_sub(sb, tid, qh, ql, kh, kl, nbase, 0);
    cp_commit();

    for (int t = 0; t < K2_SUB; t++) {
        __syncthreads();
        if (t + 1 < K2_SUB) k2_load_sub(sb, tid, qh, ql, kh, kl, nbase + (t + 1) * 64, (t + 1) & 1);
        cp_commit();
        asm volatile("cp.async.wait_group 1;" ::: "memory");
        __syncthreads();

        uint32_t stg = sb + (t & 1) * 32768;
#pragma unroll
        for (int ks = 0; ks < 4; ks++) {
            uint32_t aqh[2][4], aql[2][4];
#pragma unroll
            for (int mt = 0; mt < 2; mt++) {
                int n   = ks * 16 + an;
                int c16 = wm * 4 + mt * 2 + ac;
                uint32_t off = (uint32_t)(n * 128 + ((c16 ^ (n & 7)) << 4));
                ldsm4t(aqh[mt], stg + off);
                ldsm4t(aql[mt], stg + 8192 + off);
            }
            uint32_t bkh[2][2], bkl[2][2];
            {
                int n   = ks * 16 + bn;
                uint32_t off = (uint32_t)(n * 128 + ((bc ^ (n & 7)) << 4));
                uint32_t q[4];
                ldsm4t(q, stg + 16384 + off);
                bkh[0][0] = q[0]; bkh[0][1] = q[1]; bkh[1][0] = q[2]; bkh[1][1] = q[3];
                ldsm4t(q, stg + 24576 + off);
                bkl[0][0] = q[0]; bkl[0][1] = q[1]; bkl[1][0] = q[2]; bkl[1][1] = q[3];
            }
#pragma unroll
            for (int mt = 0; mt < 2; mt++)
#pragma unroll
                for (int nt = 0; nt < 2; nt++) {
                    mma16816(acc[mt][nt], aqh[mt], bkh[nt]);
                    mma16816(acc[mt][nt], aqh[mt], bkl[nt]);
                    mma16816(acc[mt][nt], aql[mt], bkh[nt]);
                }
        }
    }

    float* pg = g_part + ((size_t)chunk * 128 + bh) * 4096;
#pragma unroll
    for (int mt = 0; mt < 2; mt++)
#pragma unroll
        for (int nt = 0; nt < 2; nt++)
#pragma unroll
            for (int half = 0; half < 2; half++) {
                int d = wm * 32 + mt * 16 + (lane >> 2) + half * 8;
                int e = wn * 16 + nt * 8 + (lane & 3) * 2;
                float2 v;
                v.x = acc[mt][nt][half * 2 + 0];
                v.y = acc[mt][nt][half * 2 + 1];
                *(float2*)(pg + d * 64 + e) = v;
            }
}

// ---------------------------------------------------------------------------
// K2b: reduce 16 partials, scale, softmax over e; emit attn^T bf16 hi/lo.
// ---------------------------------------------------------------------------
__global__ __launch_bounds__(256) void attn_softmax_kernel()
{
    __shared__ float S[64 * 68 + 128];
    float* mrow = S + 64 * 68;
    float* irow = mrow + 64;

    const int tid = threadIdx.x;
    const int bh  = blockIdx.x;

#pragma unroll
    for (int i = 0; i < 16; i++) {
        int flat = i * 256 + tid;
        float v = 0.f;
#pragma unroll
        for (int c = 0; c < K2_NCHUNK; c++)
            v += g_part[((size_t)c * 128 + bh) * 4096 + flat];
        int d = flat >> 6, e = flat & 63;
        S[d * 68 + e] = v * 0.125f;
    }
    __syncthreads();

    if (tid < 64) {
        float m = -3.4e38f;
#pragma unroll
        for (int e = 0; e < 64; e++) m = fmaxf(m, S[tid * 68 + e]);
        float sum = 0.f;
#pragma unroll
        for (int e = 0; e < 64; e++) sum += __expf(S[tid * 68 + e] - m);
        mrow[tid] = m;
        irow[tid] = 1.f / sum;
    }
    __syncthreads();

    __nv_bfloat16* ah = g_ath + (size_t)bh * 4096;
    __nv_bfloat16* al = g_atl + (size_t)bh * 4096;
#pragma unroll
    for (int i = 0; i < 16; i++) {
        int flat = i * 256 + tid;      // flat = e*64 + d  (transposed layout)
        int e = flat >> 6, d = flat & 63;
        float a = __expf(S[d * 68 + e] - mrow[d]) * irow[d];
        __nv_bfloat16 hi = __float2bfloat16(a);
        ah[flat] = hi;
        al[flat] = __float2bfloat16(a - __bfloat162float(hi));
    }
}

// ---------------------------------------------------------------------------
// K3: out[n,e] = sum_d v[n,d] * attn[d,e] via tensor cores.
// ---------------------------------------------------------------------------
__global__ __launch_bounds__(256) void out_mma_kernel(float* __restrict__ out)
{
    __shared__ __align__(128) uint8_t smem[49152];
    uint32_t sb = smem_u32(smem);
    const int tid  = threadIdx.x;
    const int wid  = tid >> 5;
    const int lane = tid & 31;
    const int bh   = blockIdx.y;
    const int b    = bh >> 4, h = bh & 15;
    const int nt0  = blockIdx.x * 128;

    const __nv_bfloat16* agh = g_ath + (size_t)bh * 4096;
    const __nv_bfloat16* agl = g_atl + (size_t)bh * 4096;
#pragma unroll
    for (int i = 0; i < 2; i++) {
        int slot = i * 256 + tid;
        int r = slot >> 3, c = slot & 7;
        uint32_t dst = (uint32_t)(r * 128 + ((c ^ (r & 7)) << 4));
        cp16(sb + 32768 + dst, agh + r * 64 + c * 8);
        cp16(sb + 40960 + dst, agl + r * 64 + c * 8);
    }
    const __nv_bfloat16* vgh = g_qkvh + ((size_t)b * SEQ + nt0) * N_TOT + 2 * D_HID + h * 64;
    const __nv_bfloat16* vgl = g_qkvl + ((size_t)b * SEQ + nt0) * N_TOT + 2 * D_HID + h * 64;
#pragma unroll
    for (int i = 0; i < 4; i++) {
        int slot = i * 256 + tid;
        int r = slot >> 3, c = slot & 7;
        uint32_t off = (uint32_t)(r * 128 + ((c ^ (r & 7)) << 4));
        cp16(sb + off,         vgh + (size_t)r * N_TOT + c * 8);
        cp16(sb + 16384 + off, vgl + (size_t)r * N_TOT + c * 8);
    }
    cp_commit();
    asm volatile("cp.async.wait_group 0;" ::: "memory");
    __syncthreads();

    const int wm = wid >> 1;
    const int wn = wid & 1;
    const int a_r0 = wm * 32 + (lane & 15);
    const int a_h  = lane >> 4;
    const int b_r0 = wn * 32 + ((lane >> 4) << 3) + (lane & 7);
    const int b_h  = (lane >> 3) & 1;

    float acc[2][4][4];
#pragma unroll
    for (int mt = 0; mt < 2; mt++)
#pragma unroll
        for (int nt = 0; nt < 4; nt++)
#pragma unroll
            for (int j = 0; j < 4; j++) acc[mt][nt][j] = 0.f;

#pragma unroll
    for (int ks = 0; ks < 4; ks++) {
        uint32_t avh[2][4], avl[2][4];
#pragma unroll
        for (int mt = 0; mt < 2; mt++) {
            int r   = a_r0 + mt * 16;
            int c16 = ks * 2 + a_h;
            uint32_t so = (uint32_t)(r * 128 + ((c16 ^ (r & 7)) << 4));
            ldsm4(avh[mt], sb + so);
            ldsm4(avl[mt], sb + 16384 + so);
        }
        uint32_t bah[4][2], bal[4][2];
#pragma unroll
        for (int np = 0; np < 2; np++) {
            int r   = b_r0 + np * 16;
            int c16 = ks * 2 + b_h;
            uint32_t so = (uint32_t)(r * 128 + ((c16 ^ (r & 7)) << 4));
            uint32_t q[4];
            ldsm4(q, sb + 32768 + so);
            bah[np * 2 + 0][0] = q[0]; bah[np * 2 + 0][1] = q[1];
            bah[np * 2 + 1][0] = q[2]; bah[np * 2 + 1][1] = q[3];
            ldsm4(q, sb + 40960 + so);
            bal[np * 2 + 0][0] = q[0]; bal[np * 2 + 0][1] = q[1];
            bal[np * 2 + 1][0] = q[2]; bal[np * 2 + 1][1] = q[3];
        }
#pragma unroll
        for (int mt = 0; mt < 2; mt++)
#pragma unroll
            for (int nt = 0; nt < 4; nt++) {
                mma16816(acc[mt][nt], avh[mt], bah[nt]);
                mma16816(acc[mt][nt], avh[mt], bal[nt]);
                mma16816(acc[mt][nt], avl[mt], bah[nt]);
            }
    }

#pragma unroll
    for (int mt = 0; mt < 2; mt++)
#pragma unroll
        for (int half = 0; half < 2; half++) {
            int n = nt0 + wm * 32 + mt * 16 + (lane >> 2) + half * 8;
            float* orow = out + ((size_t)b * SEQ + n) * D_HID + h * 64
                          + wn * 32 + (lane & 3) * 2;
#pragma unroll
            for (int nt = 0; nt < 4; nt++) {
                float2 v;
                v.x = acc[mt][nt][half * 2 + 0];
                v.y = acc[mt][nt][half * 2 + 1];
                *(float2*)(orow + nt * 8) = v;
            }
        }
}

// ---------------------------------------------------------------------------
extern "C" void kernel_launch(void* const* d_in, const int* in_sizes, int n_in,
                              void* d_out, int out_size)
{
    const float* x    = (const float*)d_in[0];
    const float* W    = (const float*)d_in[1];
    const float* bias = (const float*)d_in[2];
    float* out = (float*)d_out;

    convert_x_kernel<<<(M_TOT * K_TOT) / (256 * 8), 256>>>(x);
    convert_w_kernel<<<dim3(N_TOT / 32, K_TOT / 32), dim3(32, 8)>>>(W);

    cudaFuncSetAttribute(qkv_mma_kernel, cudaFuncAttributeMaxDynamicSharedMemorySize, GEMM_SMEM);
    qkv_mma_kernel<<<dim3(N_TOT / BN, M_TOT / BM), 512, GEMM_SMEM>>>(bias);

    cudaFuncSetAttribute(attn_part_kernel, cudaFuncAttributeMaxDynamicSharedMemorySize, K2_SMEM);
    attn_part_kernel<<<dim3(K2_NCHUNK, BATCH * N_HEADS), 256, K2_SMEM>>>();

    attn_softmax_kernel<<<BATCH * N_HEADS, 256>>>();

    out_mma_kernel<<<dim3(SEQ / 128, BATCH * N_HEADS), 256>>>(out);
}

// round 13
// speedup vs baseline: 1.4521x; 1.3405x over previous
#include <cuda_runtime.h>
#include <cuda_fp16.h>
#include <cstdint>

#define BATCH   8
#define SEQ     4096
#define D_HID   1024
#define N_HEADS 16
#define D_HEAD  64
#define M_TOT   (BATCH * SEQ)     // 32768
#define N_TOT   (3 * D_HID)       // 3072
#define K_TOT   (D_HID)           // 1024

// Scratch (allocation-free rule: __device__ globals)
__device__ __half g_qkvh[(size_t)M_TOT * N_TOT];   // qkv hi plane (fp16)
__device__ __half g_qkvl[(size_t)M_TOT * N_TOT];   // qkv lo plane
__device__ float g_part[(size_t)16 * 128 * 4096];
__device__ __half g_ath[(size_t)128 * 4096];       // attn^T [bh][e][d] hi
__device__ __half g_atl[(size_t)128 * 4096];       // attn^T lo
__device__ __half g_x16[(size_t)M_TOT * K_TOT];    // x rounded to fp16 (single plane)
__device__ __half g_wth[(size_t)N_TOT * K_TOT];    // W^T hi (fp16)
__device__ __half g_wtl[(size_t)N_TOT * K_TOT];    // W^T lo (fp16)

// ---------------------------------------------------------------------------
// helpers
// ---------------------------------------------------------------------------
__device__ __forceinline__ uint32_t smem_u32(const void* p) {
    uint32_t a;
    asm("{ .reg .u64 t; cvta.to.shared.u64 t, %1; cvt.u32.u64 %0, t; }" : "=r"(a) : "l"(p));
    return a;
}
__device__ __forceinline__ void cp16(uint32_t smem_dst, const void* gsrc) {
    asm volatile("cp.async.cg.shared.global [%0], [%1], 16;" :: "r"(smem_dst), "l"(gsrc));
}
__device__ __forceinline__ void cp_commit() {
    asm volatile("cp.async.commit_group;" ::: "memory");
}
__device__ __forceinline__ void ldsm4(uint32_t* r, uint32_t addr) {
    asm volatile("ldmatrix.sync.aligned.m8n8.x4.shared.b16 {%0,%1,%2,%3}, [%4];"
                 : "=r"(r[0]), "=r"(r[1]), "=r"(r[2]), "=r"(r[3]) : "r"(addr));
}
__device__ __forceinline__ void ldsm4t(uint32_t* r, uint32_t addr) {
    asm volatile("ldmatrix.sync.aligned.m8n8.x4.trans.shared.b16 {%0,%1,%2,%3}, [%4];"
                 : "=r"(r[0]), "=r"(r[1]), "=r"(r[2]), "=r"(r[3]) : "r"(addr));
}
__device__ __forceinline__ void mma16816(float* c, const uint32_t* a, const uint32_t* b) {
    asm volatile("mma.sync.aligned.m16n8k16.row.col.f32.f16.f16.f32 "
                 "{%0,%1,%2,%3}, {%4,%5,%6,%7}, {%8,%9}, {%0,%1,%2,%3};"
                 : "+f"(c[0]), "+f"(c[1]), "+f"(c[2]), "+f"(c[3])
                 : "r"(a[0]), "r"(a[1]), "r"(a[2]), "r"(a[3]), "r"(b[0]), "r"(b[1]));
}
__device__ __forceinline__ uint32_t pack_h(float x, float y) {
    __half2 t = __floats2half2_rn(x, y);
    return *reinterpret_cast<uint32_t*>(&t);
}

// ---------------------------------------------------------------------------
// Conversion kernels
// ---------------------------------------------------------------------------
__global__ __launch_bounds__(256) void convert_x_kernel(const float* __restrict__ x)
{
    size_t i = ((size_t)blockIdx.x * 256 + threadIdx.x) * 8;
    float4 a = *(const float4*)(x + i);
    float4 b = *(const float4*)(x + i + 4);
    float v[8] = {a.x, a.y, a.z, a.w, b.x, b.y, b.z, b.w};
    __half h[8];
#pragma unroll
    for (int j = 0; j < 8; j++) h[j] = __float2half_rn(v[j]);
    *(uint4*)(g_x16 + i) = *(uint4*)h;
}

// W [1024, 3072] fp32 -> Wt [3072, 1024] fp16 hi/lo (transpose + exact split)
__global__ __launch_bounds__(256) void convert_w_kernel(const float* __restrict__ W)
{
    __shared__ float t[32][33];
    int x0 = blockIdx.x * 32;
    int y0 = blockIdx.y * 32;
    int tx = threadIdx.x, ty = threadIdx.y;
#pragma unroll
    for (int j = 0; j < 4; j++)
        t[ty + j * 8][tx] = W[(size_t)(y0 + ty + j * 8) * N_TOT + x0 + tx];
    __syncthreads();
#pragma unroll
    for (int j = 0; j < 4; j++) {
        int n = x0 + ty + j * 8;
        int k = y0 + tx;
        float v = t[tx][ty + j * 8];
        __half hi = __float2half_rn(v);
        __half lo = __float2half_rn(v - __half2float(hi));
        g_wth[(size_t)n * K_TOT + k] = hi;
        g_wtl[(size_t)n * K_TOT + k] = lo;
    }
}

// ---------------------------------------------------------------------------
// K1: qkv = x16 @ (Wh + Wl) + b  — fp16 2-term scheme.
// Block 256x128, BK=64, 16 chunks, 3 stages x 64KB, 512 threads, 16 warps,
// warp tile 32x64. Epilogue splits fp32 acc into fp16 hi/lo planes via smem.
// ---------------------------------------------------------------------------
#define BM 256
#define BN 128
#define BK 64
#define NCHUNK 16
#define STAGE_BYTES 65536            // xh 32K | wh 16K | wl 16K
#define XH_OFF(s) ((s) * STAGE_BYTES)
#define WH_OFF(s) ((s) * STAGE_BYTES + 32768)
#define WL_OFF(s) ((s) * STAGE_BYTES + 49152)
#define GEMM_SMEM (3 * STAGE_BYTES)  // 192 KB

__device__ __forceinline__ void load_chunk(uint32_t sb, int tid, int by, int bx, int c, int s)
{
    int koff = c * BK;
    const __half* A  = g_x16 + (size_t)(by * BM) * K_TOT + koff;
    const __half* Bh = g_wth + (size_t)(bx * BN) * K_TOT + koff;
    const __half* Bl = g_wtl + (size_t)(bx * BN) * K_TOT + koff;
#pragma unroll
    for (int i = 0; i < 4; i++) {            // A: 2048 slots
        int slot = i * 512 + tid;
        int r   = slot >> 3;
        int c16 = slot & 7;
        uint32_t off = (uint32_t)(r * 128 + ((c16 ^ (r & 7)) * 16));
        cp16(sb + XH_OFF(s) + off, A + (size_t)r * K_TOT + c16 * 8);
    }
#pragma unroll
    for (int i = 0; i < 2; i++) {            // B planes: 1024 slots each
        int slot = i * 512 + tid;
        int r   = slot >> 3;
        int c16 = slot & 7;
        uint32_t off = (uint32_t)(r * 128 + ((c16 ^ (r & 7)) * 16));
        cp16(sb + WH_OFF(s) + off, Bh + (size_t)r * K_TOT + c16 * 8);
        cp16(sb + WL_OFF(s) + off, Bl + (size_t)r * K_TOT + c16 * 8);
    }
}

__global__ __launch_bounds__(512, 1) void qkv_mma_kernel(const float* __restrict__ bias)
{
    extern __shared__ __align__(128) uint8_t smem[];
    uint32_t sb = smem_u32(smem);
    const int tid  = threadIdx.x;
    const int wid  = tid >> 5;
    const int lane = tid & 31;
    const int bx = blockIdx.x;    // N tile 0..23
    const int by = blockIdx.y;    // M tile 0..127
    const int wm = wid >> 1;      // 0..7  (32 M each)
    const int wn = wid & 1;       // 0..1  (64 N each)

    float acc[2][8][4];
#pragma unroll
    for (int mt = 0; mt < 2; mt++)
#pragma unroll
        for (int nt = 0; nt < 8; nt++)
#pragma unroll
            for (int j = 0; j < 4; j++) acc[mt][nt][j] = 0.f;

    load_chunk(sb, tid, by, bx, 0, 0); cp_commit();
    load_chunk(sb, tid, by, bx, 1, 1); cp_commit();

    const int a_r = wm * 32 + (lane & 15);
    const int a_h = lane >> 4;
    const int b_r = wn * 64 + ((lane >> 4) << 3) + (lane & 7);
    const int b_h = (lane >> 3) & 1;

    for (int ch = 0; ch < NCHUNK; ch++) {
        __syncthreads();   // all warps done with the stage load(ch+2) will fill
        if (ch + 2 < NCHUNK) load_chunk(sb, tid, by, bx, ch + 2, (ch + 2) % 3);
        cp_commit();
        asm volatile("cp.async.wait_group 2;" ::: "memory");   // chunk ch resident
        __syncthreads();

        const int s = ch % 3;
        const uint32_t xh_b = sb + XH_OFF(s);
        const uint32_t wh_b = sb + WH_OFF(s);
        const uint32_t wl_b = sb + WL_OFF(s);
#pragma unroll
        for (int ks = 0; ks < 4; ks++) {
            uint32_t a[2][4];
#pragma unroll
            for (int mt = 0; mt < 2; mt++) {
                int r   = a_r + mt * 16;
                int c16 = ks * 2 + a_h;
                uint32_t off = (uint32_t)(r * 128 + ((c16 ^ (r & 7)) * 16));
                ldsm4(a[mt], xh_b + off);
            }
#pragma unroll
            for (int np = 0; np < 4; np++) {
                int r   = b_r + np * 16;
                int c16 = ks * 2 + b_h;
                uint32_t off = (uint32_t)(r * 128 + ((c16 ^ (r & 7)) * 16));
                uint32_t qh[4], ql[4];
                ldsm4(qh, wh_b + off);
                ldsm4(ql, wl_b + off);
#pragma unroll
                for (int mt = 0; mt < 2; mt++) {
                    mma16816(acc[mt][np * 2 + 0], a[mt], qh + 0);
                    mma16816(acc[mt][np * 2 + 1], a[mt], qh + 2);
                    mma16816(acc[mt][np * 2 + 0], a[mt], ql + 0);
                    mma16816(acc[mt][np * 2 + 1], a[mt], ql + 2);
                }
            }
        }
    }
    asm volatile("cp.async.wait_group 0;" ::: "memory");
    __syncthreads();

    // ---- Epilogue via smem staging (coalesced 16B stores) ----
    const int ncol0 = bx * BN + wn * 64 + (lane & 3) * 2;
    float b0[8], b1[8];
#pragma unroll
    for (int nt = 0; nt < 8; nt++) {
        b0[nt] = __ldg(bias + ncol0 + nt * 8);
        b1[nt] = __ldg(bias + ncol0 + nt * 8 + 1);
    }
#pragma unroll
    for (int mt = 0; mt < 2; mt++)
#pragma unroll
        for (int half = 0; half < 2; half++) {
            int m = wm * 32 + mt * 16 + (lane >> 2) + half * 8;   // 0..255 (local)
#pragma unroll
            for (int nt = 0; nt < 8; nt++) {
                float vx = acc[mt][nt][half * 2 + 0] + b0[nt];
                float vy = acc[mt][nt][half * 2 + 1] + b1[nt];
                __half hx = __float2half_rn(vx);
                __half hy = __float2half_rn(vy);
                int chunk = wn * 8 + nt;                          // 0..15
                uint32_t off = (uint32_t)(m * 256 + (((chunk ^ (m & 7)) << 4))
                                          + (lane & 3) * 4);
                *(uint32_t*)(smem + off) = pack_h(vx, vy);
                *(uint32_t*)(smem + 65536 + off) =
                    pack_h(vx - __half2float(hx), vy - __half2float(hy));
            }
        }
    __syncthreads();

#pragma unroll
    for (int i = 0; i < 8; i++) {
        int slot = i * 512 + tid;           // 0..4095
        int r = slot >> 4;                  // 0..255
        int c = slot & 15;                  // 16B chunk
        uint32_t soff = (uint32_t)(r * 256 + ((c ^ (r & 7)) << 4));
        uint4 hv = *(uint4*)(smem + soff);
        uint4 lv = *(uint4*)(smem + 65536 + soff);
        size_t gbase = (size_t)(by * BM + r) * N_TOT + bx * BN + c * 8;
        *(uint4*)(g_qkvh + gbase) = hv;
        *(uint4*)(g_qkvl + gbase) = lv;
    }
}

// ---------------------------------------------------------------------------
// K2a: partial S over a 256-n chunk, fp16 3-term, ldmatrix.trans.
// grid (16, 128). 256 threads. Subtile 64n, 2-stage cp.async (64KB smem).
// ---------------------------------------------------------------------------
#define K2_SMEM 65536
#define K2_NCHUNK 16
#define K2_SUB 4

__device__ __forceinline__ void k2_load_sub(uint32_t sb, int tid,
                                            const __half* qh, const __half* ql,
                                            const __half* kh, const __half* kl,
                                            int n0, int stg)
{
    const __half* src[4] = {qh, ql, kh, kl};
    uint32_t base = sb + stg * 32768;
#pragma unroll
    for (int p = 0; p < 4; p++) {
#pragma unroll
        for (int i = 0; i < 2; i++) {
            int slot = i * 256 + tid;
            int r   = slot >> 3;
            int c16 = slot & 7;
            uint32_t off = (uint32_t)(r * 128 + ((c16 ^ (r & 7)) << 4));
            cp16(base + p * 8192 + off, src[p] + (size_t)(n0 + r) * N_TOT + c16 * 8);
        }
    }
}

__global__ __launch_bounds__(256) void attn_part_kernel()
{
    extern __shared__ __align__(128) uint8_t smem[];
    uint32_t sb = smem_u32(smem);
    const int tid   = threadIdx.x;
    const int wid   = tid >> 5;
    const int lane  = tid & 31;
    const int chunk = blockIdx.x;        // 0..15
    const int bh    = blockIdx.y;        // 0..127
    const int b     = bh >> 4, h = bh & 15;

    const __half* qh = g_qkvh + (size_t)b * SEQ * N_TOT + h * 64;
    const __half* ql = g_qkvl + (size_t)b * SEQ * N_TOT + h * 64;
    const __half* kh = qh + D_HID;
    const __half* kl = ql + D_HID;

    const int wm = wid >> 2;
    const int wn = wid & 3;

    const int an = ((lane >> 4) & 1) * 8 + (lane & 7);
    const int ac = ((lane >> 3) & 1);
    const int bn = ((lane >> 3) & 1) * 8 + (lane & 7);
    const int bc = wn * 2 + (lane >> 4);

    float acc[2][2][4];
#pragma unroll
    for (int mt = 0; mt < 2; mt++)
#pragma unroll
        for (int nt = 0; nt < 2; nt++)
#pragma unroll
            for (int j = 0; j < 4; j++) acc[mt][nt][j] = 0.f;

    const int nbase = chunk * 256;
    k2_load_sub(sb, tid, qh, ql, kh, kl, nbase, 0);
    cp_commit();

    for (int t = 0; t < K2_SUB; t++) {
        __syncthreads();
        if (t + 1 < K2_SUB) k2_load_sub(sb, tid, qh, ql, kh, kl, nbase + (t + 1) * 64, (t + 1) & 1);
        cp_commit();
        asm volatile("cp.async.wait_group 1;" ::: "memory");
        __syncthreads();

        uint32_t stg = sb + (t & 1) * 32768;
#pragma unroll
        for (int ks = 0; ks < 4; ks++) {
            uint32_t aqh[2][4], aql[2][4];
#pragma unroll
            for (int mt = 0; mt < 2; mt++) {
                int n   = ks * 16 + an;
                int c16 = wm * 4 + mt * 2 + ac;
                uint32_t off = (uint32_t)(n * 128 + ((c16 ^ (n & 7)) << 4));
                ldsm4t(aqh[mt], stg + off);
                ldsm4t(aql[mt], stg + 8192 + off);
            }
            uint32_t bkh[2][2], bkl[2][2];
            {
                int n   = ks * 16 + bn;
                uint32_t off = (uint32_t)(n * 128 + ((bc ^ (n & 7)) << 4));
                uint32_t q[4];
                ldsm4t(q, stg + 16384 + off);
                bkh[0][0] = q[0]; bkh[0][1] = q[1]; bkh[1][0] = q[2]; bkh[1][1] = q[3];
                ldsm4t(q, stg + 24576 + off);
                bkl[0][0] = q[0]; bkl[0][1] = q[1]; bkl[1][0] = q[2]; bkl[1][1] = q[3];
            }
#pragma unroll
            for (int mt = 0; mt < 2; mt++)
#pragma unroll
                for (int nt = 0; nt < 2; nt++) {
                    mma16816(acc[mt][nt], aqh[mt], bkh[nt]);
                    mma16816(acc[mt][nt], aqh[mt], bkl[nt]);
                    mma16816(acc[mt][nt], aql[mt], bkh[nt]);
                }
        }
    }

    float* pg = g_part + ((size_t)chunk * 128 + bh) * 4096;
#pragma unroll
    for (int mt = 0; mt < 2; mt++)
#pragma unroll
        for (int nt = 0; nt < 2; nt++)
#pragma unroll
            for (int half = 0; half < 2; half++) {
                int d = wm * 32 + mt * 16 + (lane >> 2) + half * 8;
                int e = wn * 16 + nt * 8 + (lane & 3) * 2;
                float2 v;
                v.x = acc[mt][nt][half * 2 + 0];
                v.y = acc[mt][nt][half * 2 + 1];
                *(float2*)(pg + d * 64 + e) = v;
            }
}

// ---------------------------------------------------------------------------
// K2b: reduce 16 partials, scale, softmax over e; emit attn^T fp16 hi/lo.
// ---------------------------------------------------------------------------
__global__ __launch_bounds__(256) void attn_softmax_kernel()
{
    __shared__ float S[64 * 68 + 128];
    float* mrow = S + 64 * 68;
    float* irow = mrow + 64;

    const int tid = threadIdx.x;
    const int bh  = blockIdx.x;

#pragma unroll
    for (int i = 0; i < 16; i++) {
        int flat = i * 256 + tid;
        float v = 0.f;
#pragma unroll
        for (int c = 0; c < K2_NCHUNK; c++)
            v += g_part[((size_t)c * 128 + bh) * 4096 + flat];
        int d = flat >> 6, e = flat & 63;
        S[d * 68 + e] = v * 0.125f;
    }
    __syncthreads();

    if (tid < 64) {
        float m = -3.4e38f;
#pragma unroll
        for (int e = 0; e < 64; e++) m = fmaxf(m, S[tid * 68 + e]);
        float sum = 0.f;
#pragma unroll
        for (int e = 0; e < 64; e++) sum += __expf(S[tid * 68 + e] - m);
        mrow[tid] = m;
        irow[tid] = 1.f / sum;
    }
    __syncthreads();

    __half* ah = g_ath + (size_t)bh * 4096;
    __half* al = g_atl + (size_t)bh * 4096;
#pragma unroll
    for (int i = 0; i < 16; i++) {
        int flat = i * 256 + tid;      // flat = e*64 + d  (transposed layout)
        int e = flat >> 6, d = flat & 63;
        float a = __expf(S[d * 68 + e] - mrow[d]) * irow[d];
        __half hi = __float2half_rn(a);
        ah[flat] = hi;
        al[flat] = __float2half_rn(a - __half2float(hi));
    }
}

// ---------------------------------------------------------------------------
// K3: out[n,e] = sum_d v[n,d] * attn[d,e], fp16 3-term, tensor cores.
// ---------------------------------------------------------------------------
__global__ __launch_bounds__(256) void out_mma_kernel(float* __restrict__ out)
{
    __shared__ __align__(128) uint8_t smem[49152];
    uint32_t sb = smem_u32(smem);
    const int tid  = threadIdx.x;
    const int wid  = tid >> 5;
    const int lane = tid & 31;
    const int bh   = blockIdx.y;
    const int b    = bh >> 4, h = bh & 15;
    const int nt0  = blockIdx.x * 128;

    const __half* agh = g_ath + (size_t)bh * 4096;
    const __half* agl = g_atl + (size_t)bh * 4096;
#pragma unroll
    for (int i = 0; i < 2; i++) {
        int slot = i * 256 + tid;
        int r = slot >> 3, c = slot & 7;
        uint32_t dst = (uint32_t)(r * 128 + ((c ^ (r & 7)) << 4));
        cp16(sb + 32768 + dst, agh + r * 64 + c * 8);
        cp16(sb + 40960 + dst, agl + r * 64 + c * 8);
    }
    const __half* vgh = g_qkvh + ((size_t)b * SEQ + nt0) * N_TOT + 2 * D_HID + h * 64;
    const __half* vgl = g_qkvl + ((size_t)b * SEQ + nt0) * N_TOT + 2 * D_HID + h * 64;
#pragma unroll
    for (int i = 0; i < 4; i++) {
        int slot = i * 256 + tid;
        int r = slot >> 3, c = slot & 7;
        uint32_t off = (uint32_t)(r * 128 + ((c ^ (r & 7)) << 4));
        cp16(sb + off,         vgh + (size_t)r * N_TOT + c * 8);
        cp16(sb + 16384 + off, vgl + (size_t)r * N_TOT + c * 8);
    }
    cp_commit();
    asm volatile("cp.async.wait_group 0;" ::: "memory");
    __syncthreads();

    const int wm = wid >> 1;
    const int wn = wid & 1;
    const int a_r0 = wm * 32 + (lane & 15);
    const int a_h  = lane >> 4;
    const int b_r0 = wn * 32 + ((lane >> 4) << 3) + (lane & 7);
    const int b_h  = (lane >> 3) & 1;

    float acc[2][4][4];
#pragma unroll
    for (int mt = 0; mt < 2; mt++)
#pragma unroll
        for (int nt = 0; nt < 4; nt++)
#pragma unroll
            for (int j = 0; j < 4; j++) acc[mt][nt][j] = 0.f;

#pragma unroll
    for (int ks = 0; ks < 4; ks++) {
        uint32_t avh[2][4], avl[2][4];
#pragma unroll
        for (int mt = 0; mt < 2; mt++) {
            int r   = a_r0 + mt * 16;
            int c16 = ks * 2 + a_h;
            uint32_t so = (uint32_t)(r * 128 + ((c16 ^ (r & 7)) << 4));
            ldsm4(avh[mt], sb + so);
            ldsm4(avl[mt], sb + 16384 + so);
        }
        uint32_t bah[4][2], bal[4][2];
#pragma unroll
        for (int np = 0; np < 2; np++) {
            int r   = b_r0 + np * 16;
            int c16 = ks * 2 + b_h;
            uint32_t so = (uint32_t)(r * 128 + ((c16 ^ (r & 7)) << 4));
            uint32_t q[4];
            ldsm4(q, sb + 32768 + so);
            bah[np * 2 + 0][0] = q[0]; bah[np * 2 + 0][1] = q[1];
            bah[np * 2 + 1][0] = q[2]; bah[np * 2 + 1][1] = q[3];
            ldsm4(q, sb + 40960 + so);
            bal[np * 2 + 0][0] = q[0]; bal[np * 2 + 0][1] = q[1];
            bal[np * 2 + 1][0] = q[2]; bal[np * 2 + 1][1] = q[3];
        }
#pragma unroll
        for (int mt = 0; mt < 2; mt++)
#pragma unroll
            for (int nt = 0; nt < 4; nt++) {
                mma16816(acc[mt][nt], avh[mt], bah[nt]);
                mma16816(acc[mt][nt], avh[mt], bal[nt]);
                mma16816(acc[mt][nt], avl[mt], bah[nt]);
            }
    }

#pragma unroll
    for (int mt = 0; mt < 2; mt++)
#pragma unroll
        for (int half = 0; half < 2; half++) {
            int n = nt0 + wm * 32 + mt * 16 + (lane >> 2) + half * 8;
            float* orow = out + ((size_t)b * SEQ + n) * D_HID + h * 64
                          + wn * 32 + (lane & 3) * 2;
#pragma unroll
            for (int nt = 0; nt < 4; nt++) {
                float2 v;
                v.x = acc[mt][nt][half * 2 + 0];
                v.y = acc[mt][nt][half * 2 + 1];
                *(float2*)(orow + nt * 8) = v;
            }
        }
}

// ---------------------------------------------------------------------------
extern "C" void kernel_launch(void* const* d_in, const int* in_sizes, int n_in,
                              void* d_out, int out_size)
{
    const float* x    = (const float*)d_in[0];
    const float* W    = (const float*)d_in[1];
    const float* bias = (const float*)d_in[2];
    float* out = (float*)d_out;

    convert_x_kernel<<<(M_TOT * K_TOT) / (256 * 8), 256>>>(x);
    convert_w_kernel<<<dim3(N_TOT / 32, K_TOT / 32), dim3(32, 8)>>>(W);

    cudaFuncSetAttribute(qkv_mma_kernel, cudaFuncAttributeMaxDynamicSharedMemorySize, GEMM_SMEM);
    qkv_mma_kernel<<<dim3(N_TOT / BN, M_TOT / BM), 512, GEMM_SMEM>>>(bias);

    cudaFuncSetAttribute(attn_part_kernel, cudaFuncAttributeMaxDynamicSharedMemorySize, K2_SMEM);
    attn_part_kernel<<<dim3(K2_NCHUNK, BATCH * N_HEADS), 256, K2_SMEM>>>();

    attn_softmax_kernel<<<BATCH * N_HEADS, 256>>>();

    out_mma_kernel<<<dim3(SEQ / 128, BATCH * N_HEADS), 256>>>(out);
}

// round 14
// speedup vs baseline: 1.9385x; 1.3350x over previous
#include <cuda_runtime.h>
#include <cuda_fp16.h>
#include <cstdint>

#define BATCH   8
#define SEQ     4096
#define D_HID   1024
#define N_HEADS 16
#define D_HEAD  64
#define M_TOT   (BATCH * SEQ)     // 32768
#define N_TOT   (3 * D_HID)       // 3072
#define K_TOT   (D_HID)           // 1024

// Scratch (allocation-free rule: __device__ globals)
__device__ __half g_x16[(size_t)M_TOT * K_TOT];       // x rounded to fp16
__device__ __half g_wth[(size_t)N_TOT * K_TOT];       // W^T hi
__device__ __half g_wtl[(size_t)N_TOT * K_TOT];       // W^T lo
__device__ __half g_vh[(size_t)M_TOT * K_TOT];        // v hi plane
__device__ __half g_vl[(size_t)M_TOT * K_TOT];        // v lo plane
__device__ __half g_Gh[(size_t)BATCH * K_TOT * K_TOT];  // Gram hi
__device__ __half g_Gl[(size_t)BATCH * K_TOT * K_TOT];  // Gram lo
__device__ __half g_Th[(size_t)BATCH * K_TOT * K_TOT];  // T = G*Wk hi
__device__ __half g_Tl[(size_t)BATCH * K_TOT * K_TOT];  // T lo
__device__ float  g_S[(size_t)128 * 4096];              // S logits (bh, 64x64)
__device__ float  g_sx[(size_t)BATCH * K_TOT];          // column sums of x
__device__ float  g_sqk[(size_t)BATCH * 2048];          // sx@Wq | sx@Wk
__device__ __half g_ath[(size_t)128 * 4096];            // attn^T hi
__device__ __half g_atl[(size_t)128 * 4096];            // attn^T lo

// ---------------------------------------------------------------------------
// helpers
// ---------------------------------------------------------------------------
__device__ __forceinline__ uint32_t smem_u32(const void* p) {
    uint32_t a;
    asm("{ .reg .u64 t; cvta.to.shared.u64 t, %1; cvt.u32.u64 %0, t; }" : "=r"(a) : "l"(p));
    return a;
}
__device__ __forceinline__ void cp16(uint32_t smem_dst, const void* gsrc) {
    asm volatile("cp.async.cg.shared.global [%0], [%1], 16;" :: "r"(smem_dst), "l"(gsrc));
}
__device__ __forceinline__ void cp_commit() {
    asm volatile("cp.async.commit_group;" ::: "memory");
}
__device__ __forceinline__ void ldsm4(uint32_t* r, uint32_t addr) {
    asm volatile("ldmatrix.sync.aligned.m8n8.x4.shared.b16 {%0,%1,%2,%3}, [%4];"
                 : "=r"(r[0]), "=r"(r[1]), "=r"(r[2]), "=r"(r[3]) : "r"(addr));
}
__device__ __forceinline__ void ldsm4t(uint32_t* r, uint32_t addr) {
    asm volatile("ldmatrix.sync.aligned.m8n8.x4.trans.shared.b16 {%0,%1,%2,%3}, [%4];"
                 : "=r"(r[0]), "=r"(r[1]), "=r"(r[2]), "=r"(r[3]) : "r"(addr));
}
__device__ __forceinline__ void mma16816(float* c, const uint32_t* a, const uint32_t* b) {
    asm volatile("mma.sync.aligned.m16n8k16.row.col.f32.f16.f16.f32 "
                 "{%0,%1,%2,%3}, {%4,%5,%6,%7}, {%8,%9}, {%0,%1,%2,%3};"
                 : "+f"(c[0]), "+f"(c[1]), "+f"(c[2]), "+f"(c[3])
                 : "r"(a[0]), "r"(a[1]), "r"(a[2]), "r"(a[3]), "r"(b[0]), "r"(b[1]));
}
__device__ __forceinline__ uint32_t pack_h(float x, float y) {
    __half2 t = __floats2half2_rn(x, y);
    return *reinterpret_cast<uint32_t*>(&t);
}

// ---------------------------------------------------------------------------
// Conversions + exact correction inputs
// ---------------------------------------------------------------------------
__global__ __launch_bounds__(256) void convert_x_kernel(const float* __restrict__ x)
{
    size_t i = ((size_t)blockIdx.x * 256 + threadIdx.x) * 8;
    float4 a = *(const float4*)(x + i);
    float4 b = *(const float4*)(x + i + 4);
    float v[8] = {a.x, a.y, a.z, a.w, b.x, b.y, b.z, b.w};
    __half h[8];
#pragma unroll
    for (int j = 0; j < 8; j++) h[j] = __float2half_rn(v[j]);
    *(uint4*)(g_x16 + i) = *(uint4*)h;
}

__global__ __launch_bounds__(256) void convert_w_kernel(const float* __restrict__ W)
{
    __shared__ float t[32][33];
    int x0 = blockIdx.x * 32;
    int y0 = blockIdx.y * 32;
    int tx = threadIdx.x, ty = threadIdx.y;
#pragma unroll
    for (int j = 0; j < 4; j++)
        t[ty + j * 8][tx] = W[(size_t)(y0 + ty + j * 8) * N_TOT + x0 + tx];
    __syncthreads();
#pragma unroll
    for (int j = 0; j < 4; j++) {
        int n = x0 + ty + j * 8;
        int k = y0 + tx;
        float v = t[tx][ty + j * 8];
        __half hi = __float2half_rn(v);
        __half lo = __float2half_rn(v - __half2float(hi));
        g_wth[(size_t)n * K_TOT + k] = hi;
        g_wtl[(size_t)n * K_TOT + k] = lo;
    }
}

// sx[b][k] = sum_n x[b][n][k]  (fp32, exact)
__global__ __launch_bounds__(256) void sum_x_kernel(const float* __restrict__ x)
{
    __shared__ float red[256];
    const int slab = blockIdx.x;      // 0..31 (32 cols each)
    const int b    = blockIdx.y;
    const int tid  = threadIdx.x;
    const int col  = slab * 32 + (tid & 31);
    const int part = tid >> 5;        // 0..7, 512 rows each
    const float* xb = x + (size_t)b * SEQ * K_TOT;
    float acc = 0.f;
    for (int r = part * 512; r < part * 512 + 512; r++)
        acc += xb[(size_t)r * K_TOT + col];
    red[tid] = acc;
    __syncthreads();
    if (tid < 32) {
        float s = 0.f;
#pragma unroll
        for (int p = 0; p < 8; p++) s += red[p * 32 + tid];
        g_sx[(size_t)b * K_TOT + slab * 32 + tid] = s;
    }
}

// sqk[b][o] = sum_k sx[b][k] * W[k][o]  for o in 0..2047 (q|k cols, exact fp32)
__global__ __launch_bounds__(256) void gemv_kernel(const float* __restrict__ W)
{
    __shared__ float sxs[1024];
    const int oslab = blockIdx.x;     // 0..7
    const int b     = blockIdx.y;
    const int tid   = threadIdx.x;
#pragma unroll
    for (int i = 0; i < 4; i++)
        sxs[i * 256 + tid] = g_sx[(size_t)b * K_TOT + i * 256 + tid];
    __syncthreads();
    const int o = oslab * 256 + tid;  // 0..2047
    float acc = 0.f;
    for (int k = 0; k < 1024; k++)
        acc += sxs[k] * __ldg(W + (size_t)k * N_TOT + o);
    g_sqk[(size_t)b * 2048 + o] = acc;
}

// ---------------------------------------------------------------------------
// K1v: v = x16 @ (Wvh + Wvl) + bv.  fp16 2-term.  Block 256x128, BK=64,
// 16 chunks, 3 stages x 64KB, 512 threads. Output g_vh/g_vl (stride 1024).
// ---------------------------------------------------------------------------
#define BM 256
#define BN 128
#define BK 64
#define NCHUNK 16
#define STAGE_BYTES 65536            // x 32K | wh 16K | wl 16K
#define XH_OFF(s) ((s) * STAGE_BYTES)
#define WH_OFF(s) ((s) * STAGE_BYTES + 32768)
#define WL_OFF(s) ((s) * STAGE_BYTES + 49152)
#define GEMM_SMEM (3 * STAGE_BYTES)  // 192 KB

__device__ __forceinline__ void v_load_chunk(uint32_t sb, int tid, int by, int bx, int c, int s)
{
    int koff = c * BK;
    const __half* A  = g_x16 + (size_t)(by * BM) * K_TOT + koff;
    const __half* Bh = g_wth + (size_t)(2048 + bx * BN) * K_TOT + koff;
    const __half* Bl = g_wtl + (size_t)(2048 + bx * BN) * K_TOT + koff;
#pragma unroll
    for (int i = 0; i < 4; i++) {
        int slot = i * 512 + tid;
        int r   = slot >> 3;
        int c16 = slot & 7;
        uint32_t off = (uint32_t)(r * 128 + ((c16 ^ (r & 7)) * 16));
        cp16(sb + XH_OFF(s) + off, A + (size_t)r * K_TOT + c16 * 8);
    }
#pragma unroll
    for (int i = 0; i < 2; i++) {
        int slot = i * 512 + tid;
        int r   = slot >> 3;
        int c16 = slot & 7;
        uint32_t off = (uint32_t)(r * 128 + ((c16 ^ (r & 7)) * 16));
        cp16(sb + WH_OFF(s) + off, Bh + (size_t)r * K_TOT + c16 * 8);
        cp16(sb + WL_OFF(s) + off, Bl + (size_t)r * K_TOT + c16 * 8);
    }
}

__global__ __launch_bounds__(512, 1) void vproj_kernel(const float* __restrict__ bias)
{
    extern __shared__ __align__(128) uint8_t smem[];
    uint32_t sb = smem_u32(smem);
    const int tid  = threadIdx.x;
    const int wid  = tid >> 5;
    const int lane = tid & 31;
    const int bx = blockIdx.x;    // 0..7
    const int by = blockIdx.y;    // 0..127
    const int wm = wid >> 1;
    const int wn = wid & 1;

    float acc[2][8][4];
#pragma unroll
    for (int mt = 0; mt < 2; mt++)
#pragma unroll
        for (int nt = 0; nt < 8; nt++)
#pragma unroll
            for (int j = 0; j < 4; j++) acc[mt][nt][j] = 0.f;

    v_load_chunk(sb, tid, by, bx, 0, 0); cp_commit();
    v_load_chunk(sb, tid, by, bx, 1, 1); cp_commit();

    const int a_r = wm * 32 + (lane & 15);
    const int a_h = lane >> 4;
    const int b_r = wn * 64 + ((lane >> 4) << 3) + (lane & 7);
    const int b_h = (lane >> 3) & 1;

    for (int ch = 0; ch < NCHUNK; ch++) {
        __syncthreads();
        if (ch + 2 < NCHUNK) v_load_chunk(sb, tid, by, bx, ch + 2, (ch + 2) % 3);
        cp_commit();
        asm volatile("cp.async.wait_group 2;" ::: "memory");
        __syncthreads();

        const int s = ch % 3;
        const uint32_t xh_b = sb + XH_OFF(s);
        const uint32_t wh_b = sb + WH_OFF(s);
        const uint32_t wl_b = sb + WL_OFF(s);
#pragma unroll
        for (int ks = 0; ks < 4; ks++) {
            uint32_t a[2][4];
#pragma unroll
            for (int mt = 0; mt < 2; mt++) {
                int r   = a_r + mt * 16;
                int c16 = ks * 2 + a_h;
                uint32_t off = (uint32_t)(r * 128 + ((c16 ^ (r & 7)) * 16));
                ldsm4(a[mt], xh_b + off);
            }
#pragma unroll
            for (int np = 0; np < 4; np++) {
                int r   = b_r + np * 16;
                int c16 = ks * 2 + b_h;
                uint32_t off = (uint32_t)(r * 128 + ((c16 ^ (r & 7)) * 16));
                uint32_t qh[4], ql[4];
                ldsm4(qh, wh_b + off);
                ldsm4(ql, wl_b + off);
#pragma unroll
                for (int mt = 0; mt < 2; mt++) {
                    mma16816(acc[mt][np * 2 + 0], a[mt], qh + 0);
                    mma16816(acc[mt][np * 2 + 1], a[mt], qh + 2);
                    mma16816(acc[mt][np * 2 + 0], a[mt], ql + 0);
                    mma16816(acc[mt][np * 2 + 1], a[mt], ql + 2);
                }
            }
        }
    }
    asm volatile("cp.async.wait_group 0;" ::: "memory");
    __syncthreads();

    // epilogue: +bias (v cols), split to fp16 hi/lo via smem, coalesced stores
    const int ncol0 = bx * BN + wn * 64 + (lane & 3) * 2;    // 0..1023 local
    float b0[8], b1[8];
#pragma unroll
    for (int nt = 0; nt < 8; nt++) {
        b0[nt] = __ldg(bias + 2048 + ncol0 + nt * 8);
        b1[nt] = __ldg(bias + 2048 + ncol0 + nt * 8 + 1);
    }
#pragma unroll
    for (int mt = 0; mt < 2; mt++)
#pragma unroll
        for (int half = 0; half < 2; half++) {
            int m = wm * 32 + mt * 16 + (lane >> 2) + half * 8;
#pragma unroll
            for (int nt = 0; nt < 8; nt++) {
                float vx = acc[mt][nt][half * 2 + 0] + b0[nt];
                float vy = acc[mt][nt][half * 2 + 1] + b1[nt];
                __half hx = __float2half_rn(vx);
                __half hy = __float2half_rn(vy);
                int chunk = wn * 8 + nt;
                uint32_t off = (uint32_t)(m * 256 + (((chunk ^ (m & 7)) << 4))
                                          + (lane & 3) * 4);
                *(uint32_t*)(smem + off) = pack_h(vx, vy);
                *(uint32_t*)(smem + 65536 + off) =
                    pack_h(vx - __half2float(hx), vy - __half2float(hy));
            }
        }
    __syncthreads();
#pragma unroll
    for (int i = 0; i < 8; i++) {
        int slot = i * 512 + tid;
        int r = slot >> 4;
        int c = slot & 15;
        uint32_t soff = (uint32_t)(r * 256 + ((c ^ (r & 7)) << 4));
        uint4 hv = *(uint4*)(smem + soff);
        uint4 lv = *(uint4*)(smem + 65536 + soff);
        size_t gbase = (size_t)(by * BM + r) * K_TOT + bx * BN + c * 8;
        *(uint4*)(g_vh + gbase) = hv;
        *(uint4*)(g_vl + gbase) = lv;
    }
}

// ---------------------------------------------------------------------------
// Gram: G_b = x16^T x16 (1-term).  Block tile 128d x 128e, 512 threads,
// 16 warps (4x4, warp tile 32x32), contract 4096 n in 64 subtiles, 2 stages.
// smem: xd [64n][256B] 16K | xe 16K per stage, 2 stages = 64KB.
// ---------------------------------------------------------------------------
#define GR_SMEM 65536

__global__ __launch_bounds__(512) void gram_kernel()
{
    extern __shared__ __align__(128) uint8_t smem[];
    uint32_t sb = smem_u32(smem);
    const int tid  = threadIdx.x;
    const int wid  = tid >> 5;
    const int lane = tid & 31;
    const int dtile = blockIdx.x >> 3;   // 0..7
    const int etile = blockIdx.x & 7;    // 0..7
    const int b     = blockIdx.y;
    const __half* xd = g_x16 + (size_t)b * SEQ * K_TOT + dtile * 128;
    const __half* xe = g_x16 + (size_t)b * SEQ * K_TOT + etile * 128;

    const int wm = wid >> 2;   // 0..3 (32 d)
    const int wn = wid & 3;    // 0..3 (32 e)
    const int an = ((lane >> 4) & 1) * 8 + (lane & 7);
    const int ac = (lane >> 3) & 1;
    const int bn = ((lane >> 3) & 1) * 8 + (lane & 7);

    float acc[2][4][4];
#pragma unroll
    for (int mt = 0; mt < 2; mt++)
#pragma unroll
        for (int nt = 0; nt < 4; nt++)
#pragma unroll
            for (int j = 0; j < 4; j++) acc[mt][nt][j] = 0.f;

    // subtile loader: 1024 slots per tile / 512 thr = 2 iters
#define GR_LOAD(t, s)                                                          \
    {                                                                          \
        uint32_t bs = sb + (s) * 32768;                                        \
        _Pragma("unroll")                                                      \
        for (int i = 0; i < 2; i++) {                                          \
            int slot = i * 512 + tid;                                          \
            int r = slot >> 4, c16 = slot & 15;                                \
            uint32_t off = (uint32_t)(r * 256 + ((c16 ^ (r & 7)) << 4));       \
            cp16(bs + off,         xd + (size_t)((t) * 64 + r) * K_TOT + c16 * 8); \
            cp16(bs + 16384 + off, xe + (size_t)((t) * 64 + r) * K_TOT + c16 * 8); \
        }                                                                      \
    }

    GR_LOAD(0, 0); cp_commit();

    for (int t = 0; t < 64; t++) {
        __syncthreads();
        if (t + 1 < 64) GR_LOAD(t + 1, (t + 1) & 1);
        cp_commit();
        asm volatile("cp.async.wait_group 1;" ::: "memory");
        __syncthreads();

        uint32_t stg = sb + (t & 1) * 32768;
#pragma unroll
        for (int ks = 0; ks < 4; ks++) {
            uint32_t a[2][4];
#pragma unroll
            for (int mt = 0; mt < 2; mt++) {
                int n   = ks * 16 + an;
                int c16 = wm * 4 + mt * 2 + ac;
                uint32_t off = (uint32_t)(n * 256 + ((c16 ^ (n & 7)) << 4));
                ldsm4t(a[mt], stg + off);
            }
            uint32_t bk2[4][2];
#pragma unroll
            for (int pair = 0; pair < 2; pair++) {
                int n   = ks * 16 + bn;
                int c16 = wn * 4 + pair * 2 + (lane >> 4);
                uint32_t off = (uint32_t)(n * 256 + ((c16 ^ (n & 7)) << 4));
                uint32_t q[4];
                ldsm4t(q, stg + 16384 + off);
                bk2[pair * 2 + 0][0] = q[0]; bk2[pair * 2 + 0][1] = q[1];
                bk2[pair * 2 + 1][0] = q[2]; bk2[pair * 2 + 1][1] = q[3];
            }
#pragma unroll
            for (int mt = 0; mt < 2; mt++)
#pragma unroll
                for (int nt = 0; nt < 4; nt++)
                    mma16816(acc[mt][nt], a[mt], bk2[nt]);
        }
    }

    // write G hi/lo planes
    const int gd0 = dtile * 128 + wm * 32;
    const int ge0 = etile * 128 + wn * 32;
#pragma unroll
    for (int mt = 0; mt < 2; mt++)
#pragma unroll
        for (int nt = 0; nt < 4; nt++)
#pragma unroll
            for (int half = 0; half < 2; half++) {
                int d = gd0 + mt * 16 + (lane >> 2) + half * 8;
                int e = ge0 + nt * 8 + (lane & 3) * 2;
                float vx = acc[mt][nt][half * 2 + 0];
                float vy = acc[mt][nt][half * 2 + 1];
                __half hx = __float2half_rn(vx);
                __half hy = __float2half_rn(vy);
                size_t idx = (size_t)b * 1048576 + (size_t)d * 1024 + e;
                *(uint32_t*)(g_Gh + idx) = pack_h(vx, vy);
                *(uint32_t*)(g_Gl + idx) =
                    pack_h(vx - __half2float(hx), vy - __half2float(hy));
            }
}

// ---------------------------------------------------------------------------
// proj1: T = (Gh+Gl) @ (Wkh+Wkl)  — 3-term, R10-style.  M=1024/batch, N=1024,
// K=1024. Block 256x128, BK=64, 16 chunks, 2 stages x 96KB, 512 threads.
// grid (8, 32): by -> (b, mtile).
// ---------------------------------------------------------------------------
#define P1_STAGE 98304               // Gh 32K | Gl 32K | Wh 16K | Wl 16K
#define P1_GH(s) ((s) * P1_STAGE)
#define P1_GL(s) ((s) * P1_STAGE + 32768)
#define P1_WH(s) ((s) * P1_STAGE + 65536)
#define P1_WL(s) ((s) * P1_STAGE + 81920)
#define P1_SMEM (2 * P1_STAGE)       // 192 KB

__device__ __forceinline__ void p1_load_chunk(uint32_t sb, int tid, int b, int m0,
                                              int bx, int c, int s)
{
    int koff = c * BK;
    const __half* Ah = g_Gh + (size_t)b * 1048576 + (size_t)m0 * 1024 + koff;
    const __half* Al = g_Gl + (size_t)b * 1048576 + (size_t)m0 * 1024 + koff;
    const __half* Bh = g_wth + (size_t)(1024 + bx * BN) * K_TOT + koff;
    const __half* Bl = g_wtl + (size_t)(1024 + bx * BN) * K_TOT + koff;
#pragma unroll
    for (int i = 0; i < 4; i++) {
        int slot = i * 512 + tid;
        int r   = slot >> 3;
        int c16 = slot & 7;
        uint32_t off = (uint32_t)(r * 128 + ((c16 ^ (r & 7)) * 16));
        cp16(sb + P1_GH(s) + off, Ah + (size_t)r * 1024 + c16 * 8);
        cp16(sb + P1_GL(s) + off, Al + (size_t)r * 1024 + c16 * 8);
    }
#pragma unroll
    for (int i = 0; i < 2; i++) {
        int slot = i * 512 + tid;
        int r   = slot >> 3;
        int c16 = slot & 7;
        uint32_t off = (uint32_t)(r * 128 + ((c16 ^ (r & 7)) * 16));
        cp16(sb + P1_WH(s) + off, Bh + (size_t)r * K_TOT + c16 * 8);
        cp16(sb + P1_WL(s) + off, Bl + (size_t)r * K_TOT + c16 * 8);
    }
}

__global__ __launch_bounds__(512, 1) void t_kernel()
{
    extern __shared__ __align__(128) uint8_t smem[];
    uint32_t sb = smem_u32(smem);
    const int tid  = threadIdx.x;
    const int wid  = tid >> 5;
    const int lane = tid & 31;
    const int bx = blockIdx.x;           // 0..7
    const int b  = blockIdx.y >> 2;      // 0..7
    const int m0 = (blockIdx.y & 3) * BM;
    const int wm = wid >> 1;
    const int wn = wid & 1;

    float acc[2][8][4];
#pragma unroll
    for (int mt = 0; mt < 2; mt++)
#pragma unroll
        for (int nt = 0; nt < 8; nt++)
#pragma unroll
            for (int j = 0; j < 4; j++) acc[mt][nt][j] = 0.f;

    p1_load_chunk(sb, tid, b, m0, bx, 0, 0);
    cp_commit();

    const int a_r = wm * 32 + (lane & 15);
    const int a_h = lane >> 4;
    const int b_r = wn * 64 + ((lane >> 4) << 3) + (lane & 7);
    const int b_h = (lane >> 3) & 1;

    for (int ch = 0; ch < NCHUNK; ch++) {
        __syncthreads();
        if (ch + 1 < NCHUNK) p1_load_chunk(sb, tid, b, m0, bx, ch + 1, (ch + 1) & 1);
        cp_commit();
        asm volatile("cp.async.wait_group 1;" ::: "memory");
        __syncthreads();

        const int s = ch & 1;
        const uint32_t gh_b = sb + P1_GH(s);
        const uint32_t gl_b = sb + P1_GL(s);
        const uint32_t wh_b = sb + P1_WH(s);
        const uint32_t wl_b = sb + P1_WL(s);
#pragma unroll
        for (int ks = 0; ks < 4; ks++) {
            uint32_t ah[2][4], al[2][4];
#pragma unroll
            for (int mt = 0; mt < 2; mt++) {
                int r   = a_r + mt * 16;
                int c16 = ks * 2 + a_h;
                uint32_t off = (uint32_t)(r * 128 + ((c16 ^ (r & 7)) * 16));
                ldsm4(ah[mt], gh_b + off);
                ldsm4(al[mt], gl_b + off);
            }
#pragma unroll
            for (int np = 0; np < 4; np++) {
                int r   = b_r + np * 16;
                int c16 = ks * 2 + b_h;
                uint32_t off = (uint32_t)(r * 128 + ((c16 ^ (r & 7)) * 16));
                uint32_t qh[4], ql[4];
                ldsm4(qh, wh_b + off);
                ldsm4(ql, wl_b + off);
#pragma unroll
                for (int mt = 0; mt < 2; mt++) {
                    mma16816(acc[mt][np * 2 + 0], ah[mt], qh + 0);
                    mma16816(acc[mt][np * 2 + 1], ah[mt], qh + 2);
                    mma16816(acc[mt][np * 2 + 0], al[mt], qh + 0);
                    mma16816(acc[mt][np * 2 + 1], al[mt], qh + 2);
                    mma16816(acc[mt][np * 2 + 0], ah[mt], ql + 0);
                    mma16816(acc[mt][np * 2 + 1], ah[mt], ql + 2);
                }
            }
        }
    }
    asm volatile("cp.async.wait_group 0;" ::: "memory");
    __syncthreads();

    // epilogue: split to Th/Tl planes via smem, coalesced stores (no bias)
#pragma unroll
    for (int mt = 0; mt < 2; mt++)
#pragma unroll
        for (int half = 0; half < 2; half++) {
            int m = wm * 32 + mt * 16 + (lane >> 2) + half * 8;
#pragma unroll
            for (int nt = 0; nt < 8; nt++) {
                float vx = acc[mt][nt][half * 2 + 0];
                float vy = acc[mt][nt][half * 2 + 1];
                __half hx = __float2half_rn(vx);
                __half hy = __float2half_rn(vy);
                int chunk = wn * 8 + nt;
                uint32_t off = (uint32_t)(m * 256 + (((chunk ^ (m & 7)) << 4))
                                          + (lane & 3) * 4);
                *(uint32_t*)(smem + off) = pack_h(vx, vy);
                *(uint32_t*)(smem + 65536 + off) =
                    pack_h(vx - __half2float(hx), vy - __half2float(hy));
            }
        }
    __syncthreads();
#pragma unroll
    for (int i = 0; i < 8; i++) {
        int slot = i * 512 + tid;
        int r = slot >> 4;
        int c = slot & 15;
        uint32_t soff = (uint32_t)(r * 256 + ((c ^ (r & 7)) << 4));
        uint4 hv = *(uint4*)(smem + soff);
        uint4 lv = *(uint4*)(smem + 65536 + soff);
        size_t gbase = (size_t)b * 1048576 + (size_t)(m0 + r) * 1024 + bx * BN + c * 8;
        *(uint4*)(g_Th + gbase) = hv;
        *(uint4*)(g_Tl + gbase) = lv;
    }
}

// ---------------------------------------------------------------------------
// proj2: S_h = Wq_h^T @ T[:, h-cols]  per (b,h). 3-term. Contract kin1=1024
// in 16 subtiles of 64. 256 threads (8 warps, 2x4). A normal ldsm (Wq rows),
// B trans ldsmt (T rows = kin). smem 32KB/stage x 2.
// ---------------------------------------------------------------------------
#define P2_SMEM 65536

__global__ __launch_bounds__(256) void s_kernel()
{
    extern __shared__ __align__(128) uint8_t smem[];
    uint32_t sb = smem_u32(smem);
    const int tid  = threadIdx.x;
    const int wid  = tid >> 5;
    const int lane = tid & 31;
    const int bh = blockIdx.x;
    const int b  = bh >> 4, h = bh & 15;

    const __half* awh = g_wth + (size_t)(h * 64) * K_TOT;
    const __half* awl = g_wtl + (size_t)(h * 64) * K_TOT;
    const __half* bth = g_Th + (size_t)b * 1048576 + h * 64;
    const __half* btl = g_Tl + (size_t)b * 1048576 + h * 64;

    const int wm = wid >> 2;   // 0..1 (32 d)
    const int wn = wid & 3;    // 0..3 (16 e)
    const int a_r = wm * 32 + (lane & 15);
    const int a_h = lane >> 4;
    const int bn = ((lane >> 3) & 1) * 8 + (lane & 7);
    const int bc = wn * 2 + (lane >> 4);

    float acc[2][2][4];
#pragma unroll
    for (int mt = 0; mt < 2; mt++)
#pragma unroll
        for (int nt = 0; nt < 2; nt++)
#pragma unroll
            for (int j = 0; j < 4; j++) acc[mt][nt][j] = 0.f;

    // stage: awh 0 | awl 8K | bth 16K | btl 24K ; 512 slots/tile, 2 iters
#define P2_LOAD(t, s)                                                           \
    {                                                                           \
        uint32_t bs = sb + (s) * 32768;                                         \
        int koff = (t) * 64;                                                    \
        _Pragma("unroll")                                                       \
        for (int i = 0; i < 2; i++) {                                           \
            int slot = i * 256 + tid;                                           \
            int r = slot >> 3, c16 = slot & 7;                                  \
            uint32_t off = (uint32_t)(r * 128 + ((c16 ^ (r & 7)) << 4));        \
            cp16(bs + off,         awh + (size_t)r * K_TOT + koff + c16 * 8);   \
            cp16(bs + 8192 + off,  awl + (size_t)r * K_TOT + koff + c16 * 8);   \
            cp16(bs + 16384 + off, bth + (size_t)(koff + r) * 1024 + c16 * 8);  \
            cp16(bs + 24576 + off, btl + (size_t)(koff + r) * 1024 + c16 * 8);  \
        }                                                                       \
    }

    P2_LOAD(0, 0); cp_commit();

    for (int t = 0; t < 16; t++) {
        __syncthreads();
        if (t + 1 < 16) P2_LOAD(t + 1, (t + 1) & 1);
        cp_commit();
        asm volatile("cp.async.wait_group 1;" ::: "memory");
        __syncthreads();

        uint32_t stg = sb + (t & 1) * 32768;
#pragma unroll
        for (int ks = 0; ks < 4; ks++) {
            uint32_t ah[2][4], al[2][4];
#pragma unroll
            for (int mt = 0; mt < 2; mt++) {
                int r   = a_r + mt * 16;
                int c16 = ks * 2 + a_h;
                uint32_t off = (uint32_t)(r * 128 + ((c16 ^ (r & 7)) << 4));
                ldsm4(ah[mt], stg + off);
                ldsm4(al[mt], stg + 8192 + off);
            }
            uint32_t bkh[2][2], bkl[2][2];
            {
                int n   = ks * 16 + bn;
                uint32_t off = (uint32_t)(n * 128 + ((bc ^ (n & 7)) << 4));
                uint32_t q[4];
                ldsm4t(q, stg + 16384 + off);
                bkh[0][0] = q[0]; bkh[0][1] = q[1]; bkh[1][0] = q[2]; bkh[1][1] = q[3];
                ldsm4t(q, stg + 24576 + off);
                bkl[0][0] = q[0]; bkl[0][1] = q[1]; bkl[1][0] = q[2]; bkl[1][1] = q[3];
            }
#pragma unroll
            for (int mt = 0; mt < 2; mt++)
#pragma unroll
                for (int nt = 0; nt < 2; nt++) {
                    mma16816(acc[mt][nt], ah[mt], bkh[nt]);
                    mma16816(acc[mt][nt], al[mt], bkh[nt]);
                    mma16816(acc[mt][nt], ah[mt], bkl[nt]);
                }
        }
    }

    float* pg = g_S + (size_t)bh * 4096;
#pragma unroll
    for (int mt = 0; mt < 2; mt++)
#pragma unroll
        for (int nt = 0; nt < 2; nt++)
#pragma unroll
            for (int half = 0; half < 2; half++) {
                int d = wm * 32 + mt * 16 + (lane >> 2) + half * 8;
                int e = wn * 16 + nt * 8 + (lane & 3) * 2;
                float2 v;
                v.x = acc[mt][nt][half * 2 + 0];
                v.y = acc[mt][nt][half * 2 + 1];
                *(float2*)(pg + d * 64 + e) = v;
            }
}

// ---------------------------------------------------------------------------
// K2b: S += bias corrections, scale, softmax over e; emit attn^T fp16 hi/lo.
// ---------------------------------------------------------------------------
__global__ __launch_bounds__(256) void attn_softmax_kernel(const float* __restrict__ bias)
{
    __shared__ float S[64 * 68 + 128];
    __shared__ float bqs[64], bks[64], sqs[64], sks[64];
    float* mrow = S + 64 * 68;
    float* irow = mrow + 64;

    const int tid = threadIdx.x;
    const int bh  = blockIdx.x;
    const int b   = bh >> 4, h = bh & 15;

    if (tid < 64) {
        bqs[tid] = __ldg(bias + h * 64 + tid);
        bks[tid] = __ldg(bias + 1024 + h * 64 + tid);
        sqs[tid] = g_sqk[(size_t)b * 2048 + h * 64 + tid];
        sks[tid] = g_sqk[(size_t)b * 2048 + 1024 + h * 64 + tid];
    }
    __syncthreads();

#pragma unroll
    for (int i = 0; i < 16; i++) {
        int flat = i * 256 + tid;
        int d = flat >> 6, e = flat & 63;
        float v = g_S[(size_t)bh * 4096 + flat]
                + bqs[d] * sks[e] + bks[e] * sqs[d]
                + 4096.0f * bqs[d] * bks[e];
        S[d * 68 + e] = v * 0.125f;
    }
    __syncthreads();

    if (tid < 64) {
        float m = -3.4e38f;
#pragma unroll
        for (int e = 0; e < 64; e++) m = fmaxf(m, S[tid * 68 + e]);
        float sum = 0.f;
#pragma unroll
        for (int e = 0; e < 64; e++) sum += __expf(S[tid * 68 + e] - m);
        mrow[tid] = m;
        irow[tid] = 1.f / sum;
    }
    __syncthreads();

    __half* ah = g_ath + (size_t)bh * 4096;
    __half* al = g_atl + (size_t)bh * 4096;
#pragma unroll
    for (int i = 0; i < 16; i++) {
        int flat = i * 256 + tid;      // flat = e*64 + d  (transposed)
        int e = flat >> 6, d = flat & 63;
        float a = __expf(S[d * 68 + e] - mrow[d]) * irow[d];
        __half hi = __float2half_rn(a);
        ah[flat] = hi;
        al[flat] = __float2half_rn(a - __half2float(hi));
    }
}

// ---------------------------------------------------------------------------
// K3: out[n,e] = sum_d v[n,d] * attn[d,e], fp16 3-term, tensor cores.
// ---------------------------------------------------------------------------
__global__ __launch_bounds__(256) void out_mma_kernel(float* __restrict__ out)
{
    __shared__ __align__(128) uint8_t smem[49152];
    uint32_t sb = smem_u32(smem);
    const int tid  = threadIdx.x;
    const int wid  = tid >> 5;
    const int lane = tid & 31;
    const int bh   = blockIdx.y;
    const int b    = bh >> 4, h = bh & 15;
    const int nt0  = blockIdx.x * 128;

    const __half* agh = g_ath + (size_t)bh * 4096;
    const __half* agl = g_atl + (size_t)bh * 4096;
#pragma unroll
    for (int i = 0; i < 2; i++) {
        int slot = i * 256 + tid;
        int r = slot >> 3, c = slot & 7;
        uint32_t dst = (uint32_t)(r * 128 + ((c ^ (r & 7)) << 4));
        cp16(sb + 32768 + dst, agh + r * 64 + c * 8);
        cp16(sb + 40960 + dst, agl + r * 64 + c * 8);
    }
    const __half* vgh = g_vh + ((size_t)(b * SEQ + nt0)) * K_TOT + h * 64;
    const __half* vgl = g_vl + ((size_t)(b * SEQ + nt0)) * K_TOT + h * 64;
#pragma unroll
    for (int i = 0; i < 4; i++) {
        int slot = i * 256 + tid;
        int r = slot >> 3, c = slot & 7;
        uint32_t off = (uint32_t)(r * 128 + ((c ^ (r & 7)) << 4));
        cp16(sb + off,         vgh + (size_t)r * K_TOT + c * 8);
        cp16(sb + 16384 + off, vgl + (size_t)r * K_TOT + c * 8);
    }
    cp_commit();
    asm volatile("cp.async.wait_group 0;" ::: "memory");
    __syncthreads();

    const int wm = wid >> 1;
    const int wn = wid & 1;
    const int a_r0 = wm * 32 + (lane & 15);
    const int a_h  = lane >> 4;
    const int b_r0 = wn * 32 + ((lane >> 4) << 3) + (lane & 7);
    const int b_h  = (lane >> 3) & 1;

    float acc[2][4][4];
#pragma unroll
    for (int mt = 0; mt < 2; mt++)
#pragma unroll
        for (int nt = 0; nt < 4; nt++)
#pragma unroll
            for (int j = 0; j < 4; j++) acc[mt][nt][j] = 0.f;

#pragma unroll
    for (int ks = 0; ks < 4; ks++) {
        uint32_t avh[2][4], avl[2][4];
#pragma unroll
        for (int mt = 0; mt < 2; mt++) {
            int r   = a_r0 + mt * 16;
            int c16 = ks * 2 + a_h;
            uint32_t so = (uint32_t)(r * 128 + ((c16 ^ (r & 7)) << 4));
            ldsm4(avh[mt], sb + so);
            ldsm4(avl[mt], sb + 16384 + so);
        }
        uint32_t bah[4][2], bal[4][2];
#pragma unroll
        for (int np = 0; np < 2; np++) {
            int r   = b_r0 + np * 16;
            int c16 = ks * 2 + b_h;
            uint32_t so = (uint32_t)(r * 128 + ((c16 ^ (r & 7)) << 4));
            uint32_t q[4];
            ldsm4(q, sb + 32768 + so);
            bah[np * 2 + 0][0] = q[0]; bah[np * 2 + 0][1] = q[1];
            bah[np * 2 + 1][0] = q[2]; bah[np * 2 + 1][1] = q[3];
            ldsm4(q, sb + 40960 + so);
            bal[np * 2 + 0][0] = q[0]; bal[np * 2 + 0][1] = q[1];
            bal[np * 2 + 1][0] = q[2]; bal[np * 2 + 1][1] = q[3];
        }
#pragma unroll
        for (int mt = 0; mt < 2; mt++)
#pragma unroll
            for (int nt = 0; nt < 4; nt++) {
                mma16816(acc[mt][nt], avh[mt], bah[nt]);
                mma16816(acc[mt][nt], avh[mt], bal[nt]);
                mma16816(acc[mt][nt], avl[mt], bah[nt]);
            }
    }

#pragma unroll
    for (int mt = 0; mt < 2; mt++)
#pragma unroll
        for (int half = 0; half < 2; half++) {
            int n = nt0 + wm * 32 + mt * 16 + (lane >> 2) + half * 8;
            float* orow = out + ((size_t)b * SEQ + n) * D_HID + h * 64
                          + wn * 32 + (lane & 3) * 2;
#pragma unroll
            for (int nt = 0; nt < 4; nt++) {
                float2 v;
                v.x = acc[mt][nt][half * 2 + 0];
                v.y = acc[mt][nt][half * 2 + 1];
                *(float2*)(orow + nt * 8) = v;
            }
        }
}

// ---------------------------------------------------------------------------
extern "C" void kernel_launch(void* const* d_in, const int* in_sizes, int n_in,
                              void* d_out, int out_size)
{
    const float* x    = (const float*)d_in[0];
    const float* W    = (const float*)d_in[1];
    const float* bias = (const float*)d_in[2];
    float* out = (float*)d_out;

    convert_x_kernel<<<(M_TOT * K_TOT) / (256 * 8), 256>>>(x);
    convert_w_kernel<<<dim3(N_TOT / 32, K_TOT / 32), dim3(32, 8)>>>(W);
    sum_x_kernel<<<dim3(32, BATCH), 256>>>(x);
    gemv_kernel<<<dim3(8, BATCH), 256>>>(W);

    cudaFuncSetAttribute(vproj_kernel, cudaFuncAttributeMaxDynamicSharedMemorySize, GEMM_SMEM);
    vproj_kernel<<<dim3(K_TOT / BN, M_TOT / BM), 512, GEMM_SMEM>>>(bias);

    cudaFuncSetAttribute(gram_kernel, cudaFuncAttributeMaxDynamicSharedMemorySize, GR_SMEM);
    gram_kernel<<<dim3(64, BATCH), 512, GR_SMEM>>>();

    cudaFuncSetAttribute(t_kernel, cudaFuncAttributeMaxDynamicSharedMemorySize, P1_SMEM);
    t_kernel<<<dim3(8, 32), 512, P1_SMEM>>>();

    cudaFuncSetAttribute(s_kernel, cudaFuncAttributeMaxDynamicSharedMemorySize, P2_SMEM);
    s_kernel<<<128, 256, P2_SMEM>>>();

    attn_softmax_kernel<<<BATCH * N_HEADS, 256>>>(bias);

    out_mma_kernel<<<dim3(SEQ / 128, BATCH * N_HEADS), 256>>>(out);
}

// round 15
// speedup vs baseline: 1.9429x; 1.0023x over previous
#include <cuda_runtime.h>
#include <cuda_fp16.h>
#include <cstdint>

#define BATCH   8
#define SEQ     4096
#define D_HID   1024
#define N_HEADS 16
#define D_HEAD  64
#define M_TOT   (BATCH * SEQ)     // 32768
#define N_TOT   (3 * D_HID)       // 3072
#define K_TOT   (D_HID)           // 1024

// Scratch (allocation-free rule: __device__ globals)
__device__ __half g_x16[(size_t)M_TOT * K_TOT];       // x rounded to fp16
__device__ __half g_wth[(size_t)N_TOT * K_TOT];       // W^T hi
__device__ __half g_wtl[(size_t)N_TOT * K_TOT];       // W^T lo
__device__ __half g_vh[(size_t)M_TOT * K_TOT];        // v hi plane
__device__ __half g_vl[(size_t)M_TOT * K_TOT];        // v lo plane
__device__ __half g_Gh[(size_t)BATCH * K_TOT * K_TOT];  // Gram hi
__device__ __half g_Gl[(size_t)BATCH * K_TOT * K_TOT];  // Gram lo
__device__ __half g_Th[(size_t)BATCH * K_TOT * K_TOT];  // T = G*Wk hi
__device__ __half g_Tl[(size_t)BATCH * K_TOT * K_TOT];  // T lo
__device__ float  g_S[(size_t)128 * 4096];              // S logits (bh, 64x64)
__device__ float  g_sx[(size_t)BATCH * K_TOT];          // column sums of x
__device__ float  g_sqk[(size_t)BATCH * 2048];          // sx@Wq | sx@Wk
__device__ __half g_ath[(size_t)128 * 4096];            // attn^T hi
__device__ __half g_atl[(size_t)128 * 4096];            // attn^T lo

// ---------------------------------------------------------------------------
// helpers
// ---------------------------------------------------------------------------
__device__ __forceinline__ uint32_t smem_u32(const void* p) {
    uint32_t a;
    asm("{ .reg .u64 t; cvta.to.shared.u64 t, %1; cvt.u32.u64 %0, t; }" : "=r"(a) : "l"(p));
    return a;
}
__device__ __forceinline__ void cp16(uint32_t smem_dst, const void* gsrc) {
    asm volatile("cp.async.cg.shared.global [%0], [%1], 16;" :: "r"(smem_dst), "l"(gsrc));
}
__device__ __forceinline__ void cp_commit() {
    asm volatile("cp.async.commit_group;" ::: "memory");
}
__device__ __forceinline__ void ldsm4(uint32_t* r, uint32_t addr) {
    asm volatile("ldmatrix.sync.aligned.m8n8.x4.shared.b16 {%0,%1,%2,%3}, [%4];"
                 : "=r"(r[0]), "=r"(r[1]), "=r"(r[2]), "=r"(r[3]) : "r"(addr));
}
__device__ __forceinline__ void ldsm4t(uint32_t* r, uint32_t addr) {
    asm volatile("ldmatrix.sync.aligned.m8n8.x4.trans.shared.b16 {%0,%1,%2,%3}, [%4];"
                 : "=r"(r[0]), "=r"(r[1]), "=r"(r[2]), "=r"(r[3]) : "r"(addr));
}
__device__ __forceinline__ void mma16816(float* c, const uint32_t* a, const uint32_t* b) {
    asm volatile("mma.sync.aligned.m16n8k16.row.col.f32.f16.f16.f32 "
                 "{%0,%1,%2,%3}, {%4,%5,%6,%7}, {%8,%9}, {%0,%1,%2,%3};"
                 : "+f"(c[0]), "+f"(c[1]), "+f"(c[2]), "+f"(c[3])
                 : "r"(a[0]), "r"(a[1]), "r"(a[2]), "r"(a[3]), "r"(b[0]), "r"(b[1]));
}
__device__ __forceinline__ uint32_t pack_h(float x, float y) {
    __half2 t = __floats2half2_rn(x, y);
    return *reinterpret_cast<uint32_t*>(&t);
}

// ---------------------------------------------------------------------------
// Conversions + exact correction inputs
// ---------------------------------------------------------------------------
__global__ __launch_bounds__(256) void convert_x_kernel(const float* __restrict__ x)
{
    size_t i = ((size_t)blockIdx.x * 256 + threadIdx.x) * 8;
    float4 a = *(const float4*)(x + i);
    float4 b = *(const float4*)(x + i + 4);
    float v[8] = {a.x, a.y, a.z, a.w, b.x, b.y, b.z, b.w};
    __half h[8];
#pragma unroll
    for (int j = 0; j < 8; j++) h[j] = __float2half_rn(v[j]);
    *(uint4*)(g_x16 + i) = *(uint4*)h;
}

__global__ __launch_bounds__(256) void convert_w_kernel(const float* __restrict__ W)
{
    __shared__ float t[32][33];
    int x0 = blockIdx.x * 32;
    int y0 = blockIdx.y * 32;
    int tx = threadIdx.x, ty = threadIdx.y;
#pragma unroll
    for (int j = 0; j < 4; j++)
        t[ty + j * 8][tx] = W[(size_t)(y0 + ty + j * 8) * N_TOT + x0 + tx];
    __syncthreads();
#pragma unroll
    for (int j = 0; j < 4; j++) {
        int n = x0 + ty + j * 8;
        int k = y0 + tx;
        float v = t[tx][ty + j * 8];
        __half hi = __float2half_rn(v);
        __half lo = __float2half_rn(v - __half2float(hi));
        g_wth[(size_t)n * K_TOT + k] = hi;
        g_wtl[(size_t)n * K_TOT + k] = lo;
    }
}

// sx[b][k] = sum_n x[b][n][k]  (fp32, exact)
__global__ __launch_bounds__(256) void sum_x_kernel(const float* __restrict__ x)
{
    __shared__ float red[256];
    const int slab = blockIdx.x;      // 0..31 (32 cols each)
    const int b    = blockIdx.y;
    const int tid  = threadIdx.x;
    const int col  = slab * 32 + (tid & 31);
    const int part = tid >> 5;        // 0..7, 512 rows each
    const float* xb = x + (size_t)b * SEQ * K_TOT;
    float acc = 0.f;
    for (int r = part * 512; r < part * 512 + 512; r++)
        acc += xb[(size_t)r * K_TOT + col];
    red[tid] = acc;
    __syncthreads();
    if (tid < 32) {
        float s = 0.f;
#pragma unroll
        for (int p = 0; p < 8; p++) s += red[p * 32 + tid];
        g_sx[(size_t)b * K_TOT + slab * 32 + tid] = s;
    }
}

// sqk[b][o] = sum_k sx[b][k] * W[k][o]  for o in 0..2047 (q|k cols, exact fp32)
__global__ __launch_bounds__(256) void gemv_kernel(const float* __restrict__ W)
{
    __shared__ float sxs[1024];
    const int oslab = blockIdx.x;     // 0..7
    const int b     = blockIdx.y;
    const int tid   = threadIdx.x;
#pragma unroll
    for (int i = 0; i < 4; i++)
        sxs[i * 256 + tid] = g_sx[(size_t)b * K_TOT + i * 256 + tid];
    __syncthreads();
    const int o = oslab * 256 + tid;  // 0..2047
    float acc = 0.f;
    for (int k = 0; k < 1024; k++)
        acc += sxs[k] * __ldg(W + (size_t)k * N_TOT + o);
    g_sqk[(size_t)b * 2048 + o] = acc;
}

// ---------------------------------------------------------------------------
// K1v: v = x16 @ (Wvh + Wvl) + bv.  fp16 2-term.  Block 256x128, BK=64,
// 16 chunks, 3 stages x 64KB, 512 threads. Output g_vh/g_vl (stride 1024).
// ---------------------------------------------------------------------------
#define BM 256
#define BN 128
#define BK 64
#define NCHUNK 16
#define STAGE_BYTES 65536            // x 32K | wh 16K | wl 16K
#define XH_OFF(s) ((s) * STAGE_BYTES)
#define WH_OFF(s) ((s) * STAGE_BYTES + 32768)
#define WL_OFF(s) ((s) * STAGE_BYTES + 49152)
#define GEMM_SMEM (3 * STAGE_BYTES)  // 192 KB

__device__ __forceinline__ void v_load_chunk(uint32_t sb, int tid, int by, int bx, int c, int s)
{
    int koff = c * BK;
    const __half* A  = g_x16 + (size_t)(by * BM) * K_TOT + koff;
    const __half* Bh = g_wth + (size_t)(2048 + bx * BN) * K_TOT + koff;
    const __half* Bl = g_wtl + (size_t)(2048 + bx * BN) * K_TOT + koff;
#pragma unroll
    for (int i = 0; i < 4; i++) {
        int slot = i * 512 + tid;
        int r   = slot >> 3;
        int c16 = slot & 7;
        uint32_t off = (uint32_t)(r * 128 + ((c16 ^ (r & 7)) * 16));
        cp16(sb + XH_OFF(s) + off, A + (size_t)r * K_TOT + c16 * 8);
    }
#pragma unroll
    for (int i = 0; i < 2; i++) {
        int slot = i * 512 + tid;
        int r   = slot >> 3;
        int c16 = slot & 7;
        uint32_t off = (uint32_t)(r * 128 + ((c16 ^ (r & 7)) * 16));
        cp16(sb + WH_OFF(s) + off, Bh + (size_t)r * K_TOT + c16 * 8);
        cp16(sb + WL_OFF(s) + off, Bl + (size_t)r * K_TOT + c16 * 8);
    }
}

__global__ __launch_bounds__(512, 1) void vproj_kernel(const float* __restrict__ bias)
{
    extern __shared__ __align__(128) uint8_t smem[];
    uint32_t sb = smem_u32(smem);
    const int tid  = threadIdx.x;
    const int wid  = tid >> 5;
    const int lane = tid & 31;
    const int bx = blockIdx.x;    // 0..7
    const int by = blockIdx.y;    // 0..127
    const int wm = wid >> 1;
    const int wn = wid & 1;

    float acc[2][8][4];
#pragma unroll
    for (int mt = 0; mt < 2; mt++)
#pragma unroll
        for (int nt = 0; nt < 8; nt++)
#pragma unroll
            for (int j = 0; j < 4; j++) acc[mt][nt][j] = 0.f;

    v_load_chunk(sb, tid, by, bx, 0, 0); cp_commit();
    v_load_chunk(sb, tid, by, bx, 1, 1); cp_commit();

    const int a_r = wm * 32 + (lane & 15);
    const int a_h = lane >> 4;
    const int b_r = wn * 64 + ((lane >> 4) << 3) + (lane & 7);
    const int b_h = (lane >> 3) & 1;

    for (int ch = 0; ch < NCHUNK; ch++) {
        __syncthreads();
        if (ch + 2 < NCHUNK) v_load_chunk(sb, tid, by, bx, ch + 2, (ch + 2) % 3);
        cp_commit();
        asm volatile("cp.async.wait_group 2;" ::: "memory");
        __syncthreads();

        const int s = ch % 3;
        const uint32_t xh_b = sb + XH_OFF(s);
        const uint32_t wh_b = sb + WH_OFF(s);
        const uint32_t wl_b = sb + WL_OFF(s);
#pragma unroll
        for (int ks = 0; ks < 4; ks++) {
            uint32_t a[2][4];
#pragma unroll
            for (int mt = 0; mt < 2; mt++) {
                int r   = a_r + mt * 16;
                int c16 = ks * 2 + a_h;
                uint32_t off = (uint32_t)(r * 128 + ((c16 ^ (r & 7)) * 16));
                ldsm4(a[mt], xh_b + off);
            }
#pragma unroll
            for (int np = 0; np < 4; np++) {
                int r   = b_r + np * 16;
                int c16 = ks * 2 + b_h;
                uint32_t off = (uint32_t)(r * 128 + ((c16 ^ (r & 7)) * 16));
                uint32_t qh[4], ql[4];
                ldsm4(qh, wh_b + off);
                ldsm4(ql, wl_b + off);
#pragma unroll
                for (int mt = 0; mt < 2; mt++) {
                    mma16816(acc[mt][np * 2 + 0], a[mt], qh + 0);
                    mma16816(acc[mt][np * 2 + 1], a[mt], qh + 2);
                    mma16816(acc[mt][np * 2 + 0], a[mt], ql + 0);
                    mma16816(acc[mt][np * 2 + 1], a[mt], ql + 2);
                }
            }
        }
    }
    asm volatile("cp.async.wait_group 0;" ::: "memory");
    __syncthreads();

    // epilogue: +bias (v cols), split to fp16 hi/lo via smem, coalesced stores
    const int ncol0 = bx * BN + wn * 64 + (lane & 3) * 2;    // 0..1023 local
    float b0[8], b1[8];
#pragma unroll
    for (int nt = 0; nt < 8; nt++) {
        b0[nt] = __ldg(bias + 2048 + ncol0 + nt * 8);
        b1[nt] = __ldg(bias + 2048 + ncol0 + nt * 8 + 1);
    }
#pragma unroll
    for (int mt = 0; mt < 2; mt++)
#pragma unroll
        for (int half = 0; half < 2; half++) {
            int m = wm * 32 + mt * 16 + (lane >> 2) + half * 8;
#pragma unroll
            for (int nt = 0; nt < 8; nt++) {
                float vx = acc[mt][nt][half * 2 + 0] + b0[nt];
                float vy = acc[mt][nt][half * 2 + 1] + b1[nt];
                __half hx = __float2half_rn(vx);
                __half hy = __float2half_rn(vy);
                int chunk = wn * 8 + nt;
                uint32_t off = (uint32_t)(m * 256 + (((chunk ^ (m & 7)) << 4))
                                          + (lane & 3) * 4);
                *(uint32_t*)(smem + off) = pack_h(vx, vy);
                *(uint32_t*)(smem + 65536 + off) =
                    pack_h(vx - __half2float(hx), vy - __half2float(hy));
            }
        }
    __syncthreads();
#pragma unroll
    for (int i = 0; i < 8; i++) {
        int slot = i * 512 + tid;
        int r = slot >> 4;
        int c = slot & 15;
        uint32_t soff = (uint32_t)(r * 256 + ((c ^ (r & 7)) << 4));
        uint4 hv = *(uint4*)(smem + soff);
        uint4 lv = *(uint4*)(smem + 65536 + soff);
        size_t gbase = (size_t)(by * BM + r) * K_TOT + bx * BN + c * 8;
        *(uint4*)(g_vh + gbase) = hv;
        *(uint4*)(g_vl + gbase) = lv;
    }
}

// ---------------------------------------------------------------------------
// Gram: G_b = x16^T x16 (1-term).  Block tile 128d x 128e, 512 threads,
// 16 warps (4x4, warp tile 32x32), contract 4096 n in 64 subtiles, 2 stages.
// smem: xd [64n][256B] 16K | xe 16K per stage, 2 stages = 64KB.
// ---------------------------------------------------------------------------
#define GR_SMEM 65536

__global__ __launch_bounds__(512) void gram_kernel()
{
    extern __shared__ __align__(128) uint8_t smem[];
    uint32_t sb = smem_u32(smem);
    const int tid  = threadIdx.x;
    const int wid  = tid >> 5;
    const int lane = tid & 31;
    const int dtile = blockIdx.x >> 3;   // 0..7
    const int etile = blockIdx.x & 7;    // 0..7
    const int b     = blockIdx.y;
    const __half* xd = g_x16 + (size_t)b * SEQ * K_TOT + dtile * 128;
    const __half* xe = g_x16 + (size_t)b * SEQ * K_TOT + etile * 128;

    const int wm = wid >> 2;   // 0..3 (32 d)
    const int wn = wid & 3;    // 0..3 (32 e)
    const int an = ((lane >> 4) & 1) * 8 + (lane & 7);
    const int ac = (lane >> 3) & 1;
    const int bn = ((lane >> 3) & 1) * 8 + (lane & 7);

    float acc[2][4][4];
#pragma unroll
    for (int mt = 0; mt < 2; mt++)
#pragma unroll
        for (int nt = 0; nt < 4; nt++)
#pragma unroll
            for (int j = 0; j < 4; j++) acc[mt][nt][j] = 0.f;

    // subtile loader: 1024 slots per tile / 512 thr = 2 iters
#define GR_LOAD(t, s)                                                          \
    {                                                                          \
        uint32_t bs = sb + (s) * 32768;                                        \
        _Pragma("unroll")                                                      \
        for (int i = 0; i < 2; i++) {                                          \
            int slot = i * 512 + tid;                                          \
            int r = slot >> 4, c16 = slot & 15;                                \
            uint32_t off = (uint32_t)(r * 256 + ((c16 ^ (r & 7)) << 4));       \
            cp16(bs + off,         xd + (size_t)((t) * 64 + r) * K_TOT + c16 * 8); \
            cp16(bs + 16384 + off, xe + (size_t)((t) * 64 + r) * K_TOT + c16 * 8); \
        }                                                                      \
    }

    GR_LOAD(0, 0); cp_commit();

    for (int t = 0; t < 64; t++) {
        __syncthreads();
        if (t + 1 < 64) GR_LOAD(t + 1, (t + 1) & 1);
        cp_commit();
        asm volatile("cp.async.wait_group 1;" ::: "memory");
        __syncthreads();

        uint32_t stg = sb + (t & 1) * 32768;
#pragma unroll
        for (int ks = 0; ks < 4; ks++) {
            uint32_t a[2][4];
#pragma unroll
            for (int mt = 0; mt < 2; mt++) {
                int n   = ks * 16 + an;
                int c16 = wm * 4 + mt * 2 + ac;
                uint32_t off = (uint32_t)(n * 256 + ((c16 ^ (n & 7)) << 4));
                ldsm4t(a[mt], stg + off);
            }
            uint32_t bk2[4][2];
#pragma unroll
            for (int pair = 0; pair < 2; pair++) {
                int n   = ks * 16 + bn;
                int c16 = wn * 4 + pair * 2 + (lane >> 4);
                uint32_t off = (uint32_t)(n * 256 + ((c16 ^ (n & 7)) << 4));
                uint32_t q[4];
                ldsm4t(q, stg + 16384 + off);
                bk2[pair * 2 + 0][0] = q[0]; bk2[pair * 2 + 0][1] = q[1];
                bk2[pair * 2 + 1][0] = q[2]; bk2[pair * 2 + 1][1] = q[3];
            }
#pragma unroll
            for (int mt = 0; mt < 2; mt++)
#pragma unroll
                for (int nt = 0; nt < 4; nt++)
                    mma16816(acc[mt][nt], a[mt], bk2[nt]);
        }
    }

    // write G hi/lo planes
    const int gd0 = dtile * 128 + wm * 32;
    const int ge0 = etile * 128 + wn * 32;
#pragma unroll
    for (int mt = 0; mt < 2; mt++)
#pragma unroll
        for (int nt = 0; nt < 4; nt++)
#pragma unroll
            for (int half = 0; half < 2; half++) {
                int d = gd0 + mt * 16 + (lane >> 2) + half * 8;
                int e = ge0 + nt * 8 + (lane & 3) * 2;
                float vx = acc[mt][nt][half * 2 + 0];
                float vy = acc[mt][nt][half * 2 + 1];
                __half hx = __float2half_rn(vx);
                __half hy = __float2half_rn(vy);
                size_t idx = (size_t)b * 1048576 + (size_t)d * 1024 + e;
                *(uint32_t*)(g_Gh + idx) = pack_h(vx, vy);
                *(uint32_t*)(g_Gl + idx) =
                    pack_h(vx - __half2float(hx), vy - __half2float(hy));
            }
}

// ---------------------------------------------------------------------------
// proj1: T = (Gh+Gl) @ (Wkh+Wkl)  — 3-term, R10-style.  M=1024/batch, N=1024,
// K=1024. Block 256x128, BK=64, 16 chunks, 2 stages x 96KB, 512 threads.
// grid (8, 32): by -> (b, mtile).
// ---------------------------------------------------------------------------
#define P1_STAGE 98304               // Gh 32K | Gl 32K | Wh 16K | Wl 16K
#define P1_GH(s) ((s) * P1_STAGE)
#define P1_GL(s) ((s) * P1_STAGE + 32768)
#define P1_WH(s) ((s) * P1_STAGE + 65536)
#define P1_WL(s) ((s) * P1_STAGE + 81920)
#define P1_SMEM (2 * P1_STAGE)       // 192 KB

__device__ __forceinline__ void p1_load_chunk(uint32_t sb, int tid, int b, int m0,
                                              int bx, int c, int s)
{
    int koff = c * BK;
    const __half* Ah = g_Gh + (size_t)b * 1048576 + (size_t)m0 * 1024 + koff;
    const __half* Al = g_Gl + (size_t)b * 1048576 + (size_t)m0 * 1024 + koff;
    const __half* Bh = g_wth + (size_t)(1024 + bx * BN) * K_TOT + koff;
    const __half* Bl = g_wtl + (size_t)(1024 + bx * BN) * K_TOT + koff;
#pragma unroll
    for (int i = 0; i < 4; i++) {
        int slot = i * 512 + tid;
        int r   = slot >> 3;
        int c16 = slot & 7;
        uint32_t off = (uint32_t)(r * 128 + ((c16 ^ (r & 7)) * 16));
        cp16(sb + P1_GH(s) + off, Ah + (size_t)r * 1024 + c16 * 8);
        cp16(sb + P1_GL(s) + off, Al + (size_t)r * 1024 + c16 * 8);
    }
#pragma unroll
    for (int i = 0; i < 2; i++) {
        int slot = i * 512 + tid;
        int r   = slot >> 3;
        int c16 = slot & 7;
        uint32_t off = (uint32_t)(r * 128 + ((c16 ^ (r & 7)) * 16));
        cp16(sb + P1_WH(s) + off, Bh + (size_t)r * K_TOT + c16 * 8);
        cp16(sb + P1_WL(s) + off, Bl + (size_t)r * K_TOT + c16 * 8);
    }
}

__global__ __launch_bounds__(512, 1) void t_kernel()
{
    extern __shared__ __align__(128) uint8_t smem[];
    uint32_t sb = smem_u32(smem);
    const int tid  = threadIdx.x;
    const int wid  = tid >> 5;
    const int lane = tid & 31;
    const int bx = blockIdx.x;           // 0..7
    const int b  = blockIdx.y >> 2;      // 0..7
    const int m0 = (blockIdx.y & 3) * BM;
    const int wm = wid >> 1;
    const int wn = wid & 1;

    float acc[2][8][4];
#pragma unroll
    for (int mt = 0; mt < 2; mt++)
#pragma unroll
        for (int nt = 0; nt < 8; nt++)
#pragma unroll
            for (int j = 0; j < 4; j++) acc[mt][nt][j] = 0.f;

    p1_load_chunk(sb, tid, b, m0, bx, 0, 0);
    cp_commit();

    const int a_r = wm * 32 + (lane & 15);
    const int a_h = lane >> 4;
    const int b_r = wn * 64 + ((lane >> 4) << 3) + (lane & 7);
    const int b_h = (lane >> 3) & 1;

    for (int ch = 0; ch < NCHUNK; ch++) {
        __syncthreads();
        if (ch + 1 < NCHUNK) p1_load_chunk(sb, tid, b, m0, bx, ch + 1, (ch + 1) & 1);
        cp_commit();
        asm volatile("cp.async.wait_group 1;" ::: "memory");
        __syncthreads();

        const int s = ch & 1;
        const uint32_t gh_b = sb + P1_GH(s);
        const uint32_t gl_b = sb + P1_GL(s);
        const uint32_t wh_b = sb + P1_WH(s);
        const uint32_t wl_b = sb + P1_WL(s);
#pragma unroll
        for (int ks = 0; ks < 4; ks++) {
            uint32_t ah[2][4], al[2][4];
#pragma unroll
            for (int mt = 0; mt < 2; mt++) {
                int r   = a_r + mt * 16;
                int c16 = ks * 2 + a_h;
                uint32_t off = (uint32_t)(r * 128 + ((c16 ^ (r & 7)) * 16));
                ldsm4(ah[mt], gh_b + off);
                ldsm4(al[mt], gl_b + off);
            }
#pragma unroll
            for (int np = 0; np < 4; np++) {
                int r   = b_r + np * 16;
                int c16 = ks * 2 + b_h;
                uint32_t off = (uint32_t)(r * 128 + ((c16 ^ (r & 7)) * 16));
                uint32_t qh[4], ql[4];
                ldsm4(qh, wh_b + off);
                ldsm4(ql, wl_b + off);
#pragma unroll
                for (int mt = 0; mt < 2; mt++) {
                    mma16816(acc[mt][np * 2 + 0], ah[mt], qh + 0);
                    mma16816(acc[mt][np * 2 + 1], ah[mt], qh + 2);
                    mma16816(acc[mt][np * 2 + 0], al[mt], qh + 0);
                    mma16816(acc[mt][np * 2 + 1], al[mt], qh + 2);
                    mma16816(acc[mt][np * 2 + 0], ah[mt], ql + 0);
                    mma16816(acc[mt][np * 2 + 1], ah[mt], ql + 2);
                }
            }
        }
    }
    asm volatile("cp.async.wait_group 0;" ::: "memory");
    __syncthreads();

    // epilogue: split to Th/Tl planes via smem, coalesced stores (no bias)
#pragma unroll
    for (int mt = 0; mt < 2; mt++)
#pragma unroll
        for (int half = 0; half < 2; half++) {
            int m = wm * 32 + mt * 16 + (lane >> 2) + half * 8;
#pragma unroll
            for (int nt = 0; nt < 8; nt++) {
                float vx = acc[mt][nt][half * 2 + 0];
                float vy = acc[mt][nt][half * 2 + 1];
                __half hx = __float2half_rn(vx);
                __half hy = __float2half_rn(vy);
                int chunk = wn * 8 + nt;
                uint32_t off = (uint32_t)(m * 256 + (((chunk ^ (m & 7)) << 4))
                                          + (lane & 3) * 4);
                *(uint32_t*)(smem + off) = pack_h(vx, vy);
                *(uint32_t*)(smem + 65536 + off) =
                    pack_h(vx - __half2float(hx), vy - __half2float(hy));
            }
        }
    __syncthreads();
#pragma unroll
    for (int i = 0; i < 8; i++) {
        int slot = i * 512 + tid;
        int r = slot >> 4;
        int c = slot & 15;
        uint32_t soff = (uint32_t)(r * 256 + ((c ^ (r & 7)) << 4));
        uint4 hv = *(uint4*)(smem + soff);
        uint4 lv = *(uint4*)(smem + 65536 + soff);
        size_t gbase = (size_t)b * 1048576 + (size_t)(m0 + r) * 1024 + bx * BN + c * 8;
        *(uint4*)(g_Th + gbase) = hv;
        *(uint4*)(g_Tl + gbase) = lv;
    }
}

// ---------------------------------------------------------------------------
// proj2: S_h = Wq_h^T @ T[:, h-cols]  per (b,h). 3-term. Contract kin1=1024
// in 16 subtiles of 64. 256 threads (8 warps, 2x4). A normal ldsm (Wq rows),
// B trans ldsmt (T rows = kin). smem 32KB/stage x 2.
// ---------------------------------------------------------------------------
#define P2_SMEM 65536

__global__ __launch_bounds__(256) void s_kernel()
{
    extern __shared__ __align__(128) uint8_t smem[];
    uint32_t sb = smem_u32(smem);
    const int tid  = threadIdx.x;
    const int wid  = tid >> 5;
    const int lane = tid & 31;
    const int bh = blockIdx.x;
    const int b  = bh >> 4, h = bh & 15;

    const __half* awh = g_wth + (size_t)(h * 64) * K_TOT;
    const __half* awl = g_wtl + (size_t)(h * 64) * K_TOT;
    const __half* bth = g_Th + (size_t)b * 1048576 + h * 64;
    const __half* btl = g_Tl + (size_t)b * 1048576 + h * 64;

    const int wm = wid >> 2;   // 0..1 (32 d)
    const int wn = wid & 3;    // 0..3 (16 e)
    const int a_r = wm * 32 + (lane & 15);
    const int a_h = lane >> 4;
    const int bn = ((lane >> 3) & 1) * 8 + (lane & 7);
    const int bc = wn * 2 + (lane >> 4);

    float acc[2][2][4];
#pragma unroll
    for (int mt = 0; mt < 2; mt++)
#pragma unroll
        for (int nt = 0; nt < 2; nt++)
#pragma unroll
            for (int j = 0; j < 4; j++) acc[mt][nt][j] = 0.f;

    // stage: awh 0 | awl 8K | bth 16K | btl 24K ; 512 slots/tile, 2 iters
#define P2_LOAD(t, s)                                                           \
    {                                                                           \
        uint32_t bs = sb + (s) * 32768;                                         \
        int koff = (t) * 64;                                                    \
        _Pragma("unroll")                                                       \
        for (int i = 0; i < 2; i++) {                                           \
            int slot = i * 256 + tid;                                           \
            int r = slot >> 3, c16 = slot & 7;                                  \
            uint32_t off = (uint32_t)(r * 128 + ((c16 ^ (r & 7)) << 4));        \
            cp16(bs + off,         awh + (size_t)r * K_TOT + koff + c16 * 8);   \
            cp16(bs + 8192 + off,  awl + (size_t)r * K_TOT + koff + c16 * 8);   \
            cp16(bs + 16384 + off, bth + (size_t)(koff + r) * 1024 + c16 * 8);  \
            cp16(bs + 24576 + off, btl + (size_t)(koff + r) * 1024 + c16 * 8);  \
        }                                                                       \
    }

    P2_LOAD(0, 0); cp_commit();

    for (int t = 0; t < 16; t++) {
        __syncthreads();
        if (t + 1 < 16) P2_LOAD(t + 1, (t + 1) & 1);
        cp_commit();
        asm volatile("cp.async.wait_group 1;" ::: "memory");
        __syncthreads();

        uint32_t stg = sb + (t & 1) * 32768;
#pragma unroll
        for (int ks = 0; ks < 4; ks++) {
            uint32_t ah[2][4], al[2][4];
#pragma unroll
            for (int mt = 0; mt < 2; mt++) {
                int r   = a_r + mt * 16;
                int c16 = ks * 2 + a_h;
                uint32_t off = (uint32_t)(r * 128 + ((c16 ^ (r & 7)) << 4));
                ldsm4(ah[mt], stg + off);
                ldsm4(al[mt], stg + 8192 + off);
            }
            uint32_t bkh[2][2], bkl[2][2];
            {
                int n   = ks * 16 + bn;
                uint32_t off = (uint32_t)(n * 128 + ((bc ^ (n & 7)) << 4));
                uint32_t q[4];
                ldsm4t(q, stg + 16384 + off);
                bkh[0][0] = q[0]; bkh[0][1] = q[1]; bkh[1][0] = q[2]; bkh[1][1] = q[3];
                ldsm4t(q, stg + 24576 + off);
                bkl[0][0] = q[0]; bkl[0][1] = q[1]; bkl[1][0] = q[2]; bkl[1][1] = q[3];
            }
#pragma unroll
            for (int mt = 0; mt < 2; mt++)
#pragma unroll
                for (int nt = 0; nt < 2; nt++) {
                    mma16816(acc[mt][nt], ah[mt], bkh[nt]);
                    mma16816(acc[mt][nt], al[mt], bkh[nt]);
                    mma16816(acc[mt][nt], ah[mt], bkl[nt]);
                }
        }
    }

    float* pg = g_S + (size_t)bh * 4096;
#pragma unroll
    for (int mt = 0; mt < 2; mt++)
#pragma unroll
        for (int nt = 0; nt < 2; nt++)
#pragma unroll
            for (int half = 0; half < 2; half++) {
                int d = wm * 32 + mt * 16 + (lane >> 2) + half * 8;
                int e = wn * 16 + nt * 8 + (lane & 3) * 2;
                float2 v;
                v.x = acc[mt][nt][half * 2 + 0];
                v.y = acc[mt][nt][half * 2 + 1];
                *(float2*)(pg + d * 64 + e) = v;
            }
}

// ---------------------------------------------------------------------------
// K2b: S += bias corrections, scale, softmax over e; emit attn^T fp16 hi/lo.
// ---------------------------------------------------------------------------
__global__ __launch_bounds__(256) void attn_softmax_kernel(const float* __restrict__ bias)
{
    __shared__ float S[64 * 68 + 128];
    __shared__ float bqs[64], bks[64], sqs[64], sks[64];
    float* mrow = S + 64 * 68;
    float* irow = mrow + 64;

    const int tid = threadIdx.x;
    const int bh  = blockIdx.x;
    const int b   = bh >> 4, h = bh & 15;

    if (tid < 64) {
        bqs[tid] = __ldg(bias + h * 64 + tid);
        bks[tid] = __ldg(bias + 1024 + h * 64 + tid);
        sqs[tid] = g_sqk[(size_t)b * 2048 + h * 64 + tid];
        sks[tid] = g_sqk[(size_t)b * 2048 + 1024 + h * 64 + tid];
    }
    __syncthreads();

#pragma unroll
    for (int i = 0; i < 16; i++) {
        int flat = i * 256 + tid;
        int d = flat >> 6, e = flat & 63;
        float v = g_S[(size_t)bh * 4096 + flat]
                + bqs[d] * sks[e] + bks[e] * sqs[d]
                + 4096.0f * bqs[d] * bks[e];
        S[d * 68 + e] = v * 0.125f;
    }
    __syncthreads();

    if (tid < 64) {
        float m = -3.4e38f;
#pragma unroll
        for (int e = 0; e < 64; e++) m = fmaxf(m, S[tid * 68 + e]);
        float sum = 0.f;
#pragma unroll
        for (int e = 0; e < 64; e++) sum += __expf(S[tid * 68 + e] - m);
        mrow[tid] = m;
        irow[tid] = 1.f / sum;
    }
    __syncthreads();

    __half* ah = g_ath + (size_t)bh * 4096;
    __half* al = g_atl + (size_t)bh * 4096;
#pragma unroll
    for (int i = 0; i < 16; i++) {
        int flat = i * 256 + tid;      // flat = e*64 + d  (transposed)
        int e = flat >> 6, d = flat & 63;
        float a = __expf(S[d * 68 + e] - mrow[d]) * irow[d];
        __half hi = __float2half_rn(a);
        ah[flat] = hi;
        al[flat] = __float2half_rn(a - __half2float(hi));
    }
}

// ---------------------------------------------------------------------------
// K3: out[n,e] = sum_d v[n,d] * attn[d,e], fp16 3-term, tensor cores.
// ---------------------------------------------------------------------------
__global__ __launch_bounds__(256) void out_mma_kernel(float* __restrict__ out)
{
    __shared__ __align__(128) uint8_t smem[49152];
    uint32_t sb = smem_u32(smem);
    const int tid  = threadIdx.x;
    const int wid  = tid >> 5;
    const int lane = tid & 31;
    const int bh   = blockIdx.y;
    const int b    = bh >> 4, h = bh & 15;
    const int nt0  = blockIdx.x * 128;

    const __half* agh = g_ath + (size_t)bh * 4096;
    const __half* agl = g_atl + (size_t)bh * 4096;
#pragma unroll
    for (int i = 0; i < 2; i++) {
        int slot = i * 256 + tid;
        int r = slot >> 3, c = slot & 7;
        uint32_t dst = (uint32_t)(r * 128 + ((c ^ (r & 7)) << 4));
        cp16(sb + 32768 + dst, agh + r * 64 + c * 8);
        cp16(sb + 40960 + dst, agl + r * 64 + c * 8);
    }
    const __half* vgh = g_vh + ((size_t)(b * SEQ + nt0)) * K_TOT + h * 64;
    const __half* vgl = g_vl + ((size_t)(b * SEQ + nt0)) * K_TOT + h * 64;
#pragma unroll
    for (int i = 0; i < 4; i++) {
        int slot = i * 256 + tid;
        int r = slot >> 3, c = slot & 7;
        uint32_t off = (uint32_t)(r * 128 + ((c ^ (r & 7)) << 4));
        cp16(sb + off,         vgh + (size_t)r * K_TOT + c * 8);
        cp16(sb + 16384 + off, vgl + (size_t)r * K_TOT + c * 8);
    }
    cp_commit();
    asm volatile("cp.async.wait_group 0;" ::: "memory");
    __syncthreads();

    const int wm = wid >> 1;
    const int wn = wid & 1;
    const int a_r0 = wm * 32 + (lane & 15);
    const int a_h  = lane >> 4;
    const int b_r0 = wn * 32 + ((lane >> 4) << 3) + (lane & 7);
    const int b_h  = (lane >> 3) & 1;

    float acc[2][4][4];
#pragma unroll
    for (int mt = 0; mt < 2; mt++)
#pragma unroll
        for (int nt = 0; nt < 4; nt++)
#pragma unroll
            for (int j = 0; j < 4; j++) acc[mt][nt][j] = 0.f;

#pragma unroll
    for (int ks = 0; ks < 4; ks++) {
        uint32_t avh[2][4], avl[2][4];
#pragma unroll
        for (int mt = 0; mt < 2; mt++) {
            int r   = a_r0 + mt * 16;
            int c16 = ks * 2 + a_h;
            uint32_t so = (uint32_t)(r * 128 + ((c16 ^ (r & 7)) << 4));
            ldsm4(avh[mt], sb + so);
            ldsm4(avl[mt], sb + 16384 + so);
        }
        uint32_t bah[4][2], bal[4][2];
#pragma unroll
        for (int np = 0; np < 2; np++) {
            int r   = b_r0 + np * 16;
            int c16 = ks * 2 + b_h;
            uint32_t so = (uint32_t)(r * 128 + ((c16 ^ (r & 7)) << 4));
            uint32_t q[4];
            ldsm4(q, sb + 32768 + so);
            bah[np * 2 + 0][0] = q[0]; bah[np * 2 + 0][1] = q[1];
            bah[np * 2 + 1][0] = q[2]; bah[np * 2 + 1][1] = q[3];
            ldsm4(q, sb + 40960 + so);
            bal[np * 2 + 0][0] = q[0]; bal[np * 2 + 0][1] = q[1];
            bal[np * 2 + 1][0] = q[2]; bal[np * 2 + 1][1] = q[3];
        }
#pragma unroll
        for (int mt = 0; mt < 2; mt++)
#pragma unroll
            for (int nt = 0; nt < 4; nt++) {
                mma16816(acc[mt][nt], avh[mt], bah[nt]);
                mma16816(acc[mt][nt], avh[mt], bal[nt]);
                mma16816(acc[mt][nt], avl[mt], bah[nt]);
            }
    }

#pragma unroll
    for (int mt = 0; mt < 2; mt++)
#pragma unroll
        for (int half = 0; half < 2; half++) {
            int n = nt0 + wm * 32 + mt * 16 + (lane >> 2) + half * 8;
            float* orow = out + ((size_t)b * SEQ + n) * D_HID + h * 64
                          + wn * 32 + (lane & 3) * 2;
#pragma unroll
            for (int nt = 0; nt < 4; nt++) {
                float2 v;
                v.x = acc[mt][nt][half * 2 + 0];
                v.y = acc[mt][nt][half * 2 + 1];
                *(float2*)(orow + nt * 8) = v;
            }
        }
}

// ---------------------------------------------------------------------------
extern "C" void kernel_launch(void* const* d_in, const int* in_sizes, int n_in,
                              void* d_out, int out_size)
{
    const float* x    = (const float*)d_in[0];
    const float* W    = (const float*)d_in[1];
    const float* bias = (const float*)d_in[2];
    float* out = (float*)d_out;

    convert_x_kernel<<<(M_TOT * K_TOT) / (256 * 8), 256>>>(x);
    convert_w_kernel<<<dim3(N_TOT / 32, K_TOT / 32), dim3(32, 8)>>>(W);
    sum_x_kernel<<<dim3(32, BATCH), 256>>>(x);
    gemv_kernel<<<dim3(8, BATCH), 256>>>(W);

    cudaFuncSetAttribute(vproj_kernel, cudaFuncAttributeMaxDynamicSharedMemorySize, GEMM_SMEM);
    vproj_kernel<<<dim3(K_TOT / BN, M_TOT / BM), 512, GEMM_SMEM>>>(bias);

    cudaFuncSetAttribute(gram_kernel, cudaFuncAttributeMaxDynamicSharedMemorySize, GR_SMEM);
    gram_kernel<<<dim3(64, BATCH), 512, GR_SMEM>>>();

    cudaFuncSetAttribute(t_kernel, cudaFuncAttributeMaxDynamicSharedMemorySize, P1_SMEM);
    t_kernel<<<dim3(8, 32), 512, P1_SMEM>>>();

    cudaFuncSetAttribute(s_kernel, cudaFuncAttributeMaxDynamicSharedMemorySize, P2_SMEM);
    s_kernel<<<128, 256, P2_SMEM>>>();

    attn_softmax_kernel<<<BATCH * N_HEADS, 256>>>(bias);

    out_mma_kernel<<<dim3(SEQ / 128, BATCH * N_HEADS), 256>>>(out);
}